// round 14
// baseline (speedup 1.0000x reference)
#include <cuda_runtime.h>
#include <cuda_fp16.h>
#include <cstdint>
#include <math.h>

#define N_NODES 50000
#define E_EDGES 800000
#define H 128
#define MF 276
#define NTILES64 (E_EDGES / 64)             // 12500 64-edge tiles
#define NSTREAMS 148                        // 74 CTAs/mode x 2 groups
#define NODE_TILES ((N_NODES + 127) / 128)  // 391

// ---------------------------------------------------------------------------
__device__ float  g_hagg[N_NODES * H];
__device__ float  g_xagg[N_NODES * 3];
__device__ __half g_h16[N_NODES * H];
__device__ __half g_a16[E_EDGES * 16];
__device__ __half g_W1e[288 * 136];
__device__ __half g_W1c[288 * 136];
__device__ __half g_We2[128 * 136];
__device__ __half g_Wc2[128 * 136];
__device__ __half g_Wn1[256 * 136];
__device__ __half g_Wn2[128 * 136];
__device__ __half g_P1e[N_NODES * H];
__device__ __half g_P2e[N_NODES * H];
__device__ __half g_P1c[N_NODES * H];
__device__ __half g_P2c[N_NODES * H];

__device__ __forceinline__ uint32_t smem_u32(const void* p) {
    uint32_t a;
    asm("{ .reg .u64 t; cvta.to.shared.u64 t, %1; cvt.u32.u64 %0, t; }"
        : "=r"(a) : "l"(p));
    return a;
}
__device__ __forceinline__ float tanh_f(float x) {
    float y;
    asm("tanh.approx.f32 %0, %1;" : "=f"(y) : "f"(x));
    return y;
}
__device__ __forceinline__ float sigmoid_f(float x) {
    return fmaf(0.5f, tanh_f(0.5f * x), 0.5f);
}
// packed silu: silu(v) = hv + hv*tanh(hv), hv = v/2   (1 MUFU per 2 values)
__device__ __forceinline__ half2 silu2(float a, float b) {
    half2 hv = __floats2half2_rn(0.5f * a, 0.5f * b);
    uint32_t hu = *(uint32_t*)&hv;
    uint32_t tu;
    asm("tanh.approx.f16x2 %0, %1;" : "=r"(tu) : "r"(hu));
    half2 t = *(half2*)&tu;
    return __hfma2(hv, t, hv);
}
__device__ __forceinline__ void red_add_v4(float* p, float a, float b, float c, float d) {
    asm volatile("red.global.add.v4.f32 [%0], {%1,%2,%3,%4};"
        :: "l"(p), "f"(a), "f"(b), "f"(c), "f"(d) : "memory");
}
#define GBAR(id) asm volatile("bar.sync %0, 256;" :: "r"(id) : "memory")

// ---------------------------------------------------------------------------
// Group GEMM (fp32 acc): 8 warps in 2(M)x4(N); C tile 64x128.
// ---------------------------------------------------------------------------
__device__ __forceinline__ void zero_acc(float (&acc)[2][4][4]) {
#pragma unroll
    for (int mt = 0; mt < 2; ++mt)
#pragma unroll
        for (int nt = 0; nt < 4; ++nt)
#pragma unroll
            for (int i = 0; i < 4; ++i) acc[mt][nt][i] = 0.f;
}

__device__ __forceinline__ void gemm_g(uint32_t aBase, int aStride,
                                       uint32_t bBase, int ksteps,
                                       float (&acc)[2][4][4])
{
    const int lane = threadIdx.x & 31;
    const int wid  = (threadIdx.x >> 5) & 7;
    const int wm   = wid & 1;
    const int wn   = wid >> 1;
    const int arow = wm * 32 + (lane & 15);
    const int acoff = (lane & 16) ? 8 : 0;
    const int brow = lane & 15;
    const int bcol = wn * 32 + ((lane & 16) ? 8 : 0);

    for (int ks = 0; ks < ksteps; ++ks) {
        const int k0 = ks * 16;
        uint32_t a[2][4];
#pragma unroll
        for (int mt = 0; mt < 2; ++mt) {
            uint32_t ad = aBase + (uint32_t)(((arow + mt * 16) * aStride + k0 + acoff) * 2);
            asm volatile("ldmatrix.sync.aligned.m8n8.x4.shared.b16 {%0,%1,%2,%3}, [%4];"
                : "=r"(a[mt][0]), "=r"(a[mt][1]), "=r"(a[mt][2]), "=r"(a[mt][3]) : "r"(ad));
        }
        uint32_t b[4][2];
#pragma unroll
        for (int nt2 = 0; nt2 < 2; ++nt2) {
            uint32_t bd = bBase + (uint32_t)(((k0 + brow) * 136 + bcol + nt2 * 16) * 2);
            asm volatile("ldmatrix.sync.aligned.m8n8.x4.trans.shared.b16 {%0,%1,%2,%3}, [%4];"
                : "=r"(b[2 * nt2][0]), "=r"(b[2 * nt2][1]),
                  "=r"(b[2 * nt2 + 1][0]), "=r"(b[2 * nt2 + 1][1]) : "r"(bd));
        }
#pragma unroll
        for (int mt = 0; mt < 2; ++mt)
#pragma unroll
            for (int nt = 0; nt < 4; ++nt)
                asm volatile("mma.sync.aligned.m16n8k16.row.col.f32.f16.f16.f32 "
                    "{%0,%1,%2,%3}, {%4,%5,%6,%7}, {%8,%9}, {%0,%1,%2,%3};"
                    : "+f"(acc[mt][nt][0]), "+f"(acc[mt][nt][1]),
                      "+f"(acc[mt][nt][2]), "+f"(acc[mt][nt][3])
                    : "r"(a[mt][0]), "r"(a[mt][1]), "r"(a[mt][2]), "r"(a[mt][3]),
                      "r"(b[nt][0]), "r"(b[nt][1]));
    }
}

// E1: act = silu(acc + Ps + Pd + b1)   (packed tanh)
__device__ __forceinline__ void epi_fuse_g(const float (&acc)[2][4][4],
                                           const __half* __restrict__ Ps,
                                           const __half* __restrict__ Pd,
                                           const float* __restrict__ sb, __half* act)
{
    const int lane = threadIdx.x & 31;
    const int wid  = (threadIdx.x >> 5) & 7;
    const int wm = wid & 1, wn = wid >> 1;
#pragma unroll
    for (int mt = 0; mt < 2; ++mt)
#pragma unroll
        for (int nt = 0; nt < 4; ++nt) {
            const int row = wm * 32 + mt * 16 + (lane >> 2);
            const int col = wn * 32 + nt * 8 + (lane & 3) * 2;
            const float b0 = sb[col], b1 = sb[col + 1];
#pragma unroll
            for (int rr = 0; rr < 2; ++rr) {
                const int r = row + rr * 8;
                float2 ps = __half22float2(*(const half2*)(Ps + r * 136 + col));
                float2 pd = __half22float2(*(const half2*)(Pd + r * 136 + col));
                float v0 = acc[mt][nt][2 * rr + 0] + ps.x + pd.x + b0;
                float v1 = acc[mt][nt][2 * rr + 1] + ps.y + pd.y + b1;
                *(half2*)(act + r * 136 + col) = silu2(v0, v1);
            }
        }
}

// ---------------------------------------------------------------------------
// 512-thread GEMM (16 warps 4x4), C tile 128x128
// ---------------------------------------------------------------------------
__device__ __forceinline__ void zero_acc32(float (&acc)[2][4][4]) { zero_acc(acc); }

__device__ __forceinline__ void gemm512(uint32_t aBase, int aStride,
                                        uint32_t bBase, int ksteps,
                                        float (&acc)[2][4][4])
{
    const int lane = threadIdx.x & 31;
    const int wid  = threadIdx.x >> 5;
    const int wm   = wid & 3;
    const int wn   = wid >> 2;
    const int arow = wm * 32 + (lane & 15);
    const int acoff = (lane & 16) ? 8 : 0;
    const int brow = lane & 15;
    const int bcol = wn * 32 + ((lane & 16) ? 8 : 0);

    for (int ks = 0; ks < ksteps; ++ks) {
        const int k0 = ks * 16;
        uint32_t a[2][4];
#pragma unroll
        for (int mt = 0; mt < 2; ++mt) {
            uint32_t ad = aBase + (uint32_t)(((arow + mt * 16) * aStride + k0 + acoff) * 2);
            asm volatile("ldmatrix.sync.aligned.m8n8.x4.shared.b16 {%0,%1,%2,%3}, [%4];"
                : "=r"(a[mt][0]), "=r"(a[mt][1]), "=r"(a[mt][2]), "=r"(a[mt][3]) : "r"(ad));
        }
        uint32_t b[4][2];
#pragma unroll
        for (int nt2 = 0; nt2 < 2; ++nt2) {
            uint32_t bd = bBase + (uint32_t)(((k0 + brow) * 136 + bcol + nt2 * 16) * 2);
            asm volatile("ldmatrix.sync.aligned.m8n8.x4.trans.shared.b16 {%0,%1,%2,%3}, [%4];"
                : "=r"(b[2 * nt2][0]), "=r"(b[2 * nt2][1]),
                  "=r"(b[2 * nt2 + 1][0]), "=r"(b[2 * nt2 + 1][1]) : "r"(bd));
        }
#pragma unroll
        for (int mt = 0; mt < 2; ++mt)
#pragma unroll
            for (int nt = 0; nt < 4; ++nt)
                asm volatile("mma.sync.aligned.m16n8k16.row.col.f32.f16.f16.f32 "
                    "{%0,%1,%2,%3}, {%4,%5,%6,%7}, {%8,%9}, {%0,%1,%2,%3};"
                    : "+f"(acc[mt][nt][0]), "+f"(acc[mt][nt][1]),
                      "+f"(acc[mt][nt][2]), "+f"(acc[mt][nt][3])
                    : "r"(a[mt][0]), "r"(a[mt][1]), "r"(a[mt][2]), "r"(a[mt][3]),
                      "r"(b[nt][0]), "r"(b[nt][1]));
    }
}

// ---------------------------------------------------------------------------
__global__ void prep_kernel(const float* __restrict__ hmat, const float* __restrict__ amat,
                            const float* __restrict__ We1, const float* __restrict__ Wc1,
                            const float* __restrict__ We2, const float* __restrict__ Wc2,
                            const float* __restrict__ Wn1, const float* __restrict__ Wn2)
{
    const int stride = gridDim.x * blockDim.x;
    const int tid0 = blockIdx.x * blockDim.x + threadIdx.x;
    const __half hz = __float2half_rn(0.f);
    for (int i = tid0; i < N_NODES * H / 2; i += stride) {
        float2 v = ((const float2*)hmat)[i];
        ((half2*)g_h16)[i] = __floats2half2_rn(v.x, v.y);
    }
    for (int i = tid0; i < E_EDGES * 8; i += stride) {
        float2 v = ((const float2*)amat)[i];
        ((half2*)g_a16)[i] = __floats2half2_rn(v.x, v.y);
    }
    for (int i = tid0; i < 288 * 136; i += stride) {
        int k = i / 136, n = i % 136;
        bool ok = (k < MF) && (n < 128);
        g_W1e[i] = ok ? __float2half_rn(We1[k * 128 + n]) : hz;
        g_W1c[i] = ok ? __float2half_rn(Wc1[k * 128 + n]) : hz;
    }
    for (int i = tid0; i < 256 * 136; i += stride) {
        int k = i / 136, n = i % 136;
        g_Wn1[i] = (n < 128) ? __float2half_rn(Wn1[k * 128 + n]) : hz;
    }
    for (int i = tid0; i < 128 * 136; i += stride) {
        int k = i / 136, n = i % 136;
        bool ok = (n < 128);
        g_We2[i] = ok ? __float2half_rn(We2[k * 128 + n]) : hz;
        g_Wc2[i] = ok ? __float2half_rn(Wc2[k * 128 + n]) : hz;
        g_Wn2[i] = ok ? __float2half_rn(Wn2[k * 128 + n]) : hz;
    }
    for (int i = tid0; i < N_NODES * H; i += stride) g_hagg[i] = 0.f;
    for (int i = tid0; i < N_NODES * 3; i += stride) g_xagg[i] = 0.f;
}

// ---------------------------------------------------------------------------
// precompute: P1e/P2e/P1c/P2c = h @ {We1_top, We1_bot, Wc1_top, Wc1_bot}
// ---------------------------------------------------------------------------
#define PC_A     0
#define PC_W     34816
#define PC_SMEM  174080

__global__ void __launch_bounds__(512, 1)
precompute_kernel()
{
    extern __shared__ __align__(16) char sm[];
    __half* A  = (__half*)(sm + PC_A);
    const uint32_t aU = smem_u32(A);
    const uint32_t wU = smem_u32(sm + PC_W);
    const int tid = threadIdx.x;

    for (int i = tid; i < 4352; i += 512)
        ((float4*)(sm + PC_W))[i] = ((const float4*)g_W1e)[i];
    for (int i = tid; i < 4352; i += 512)
        ((float4*)(sm + PC_W + 69632))[i] = ((const float4*)g_W1c)[i];
    __syncthreads();

    const int lane = tid & 31;
    const int wid  = tid >> 5;
    const int wm = wid & 3, wn = wid >> 2;
    __half* gP[4] = { g_P1e, g_P2e, g_P1c, g_P2c };
    float acc[2][4][4];

    for (int t = blockIdx.x; t < NODE_TILES; t += 148) {
        const int n0 = t * 128;
#pragma unroll
        for (int i = 0; i < 4; ++i) {
            const int idx = tid + i * 512;
            const int el = idx >> 4, c = idx & 15;
            const int n = n0 + el;
            float4 v = make_float4(0.f, 0.f, 0.f, 0.f);
            if (n < N_NODES) v = *(const float4*)(g_h16 + (size_t)n * 128 + c * 8);
            *(float4*)((char*)A + el * 272 + c * 16) = v;
        }
        __syncthreads();

#pragma unroll
        for (int j = 0; j < 4; ++j) {
            zero_acc32(acc);
            gemm512(aU, 136, wU + j * 34816, 8, acc);
            __half* P = gP[j];
#pragma unroll
            for (int mt = 0; mt < 2; ++mt)
#pragma unroll
                for (int nt = 0; nt < 4; ++nt) {
                    const int row = wm * 32 + mt * 16 + (lane >> 2);
                    const int col = wn * 32 + nt * 8 + (lane & 3) * 2;
                    int n = n0 + row;
                    if (n < N_NODES)
                        *(half2*)(P + (size_t)n * 128 + col) =
                            __floats2half2_rn(acc[mt][nt][0], acc[mt][nt][1]);
                    n = n0 + row + 8;
                    if (n < N_NODES)
                        *(half2*)(P + (size_t)n * 128 + col) =
                            __floats2half2_rn(acc[mt][nt][2], acc[mt][nt][3]);
                }
        }
        __syncthreads();
    }
}

// ---------------------------------------------------------------------------
// Fat persistent edge kernel: factorized layer-1, 3 barriers/tile.
// ---------------------------------------------------------------------------
#define EOF_W1S   0           // 32 x 136 h = 8704
#define EOF_W2    8704        // 34816
#define EOF_B1    43520
#define EOF_B2    44032
#define EOF_HW    44544
#define EOF_GRP   45056
#define GRP_PS    0           // 64 x 136 h = 17408
#define GRP_PD    17408
#define GRP_FSM   34816       // 64 x 40 h = 5120
#define GRP_ACT   39936       // 17408
#define GRP_ACT2  57344       // 17408
#define GRP_SD    74752       // 2 x 1024
#define GRP_SIDX  76800       // 2 x 512
#define GRP_SPART 77824       // 64 x 4 f = 1024
#define GRP_SIZE  78848
#define EDGE_SMEM (EOF_GRP + 2 * GRP_SIZE)   // 202752

__global__ void __launch_bounds__(512, 1)
edge_fat_kernel(const float* __restrict__ coords,
                const int* __restrict__ src, const int* __restrict__ dst,
                const __half* __restrict__ gW1e, const __half* __restrict__ gW2e,
                const __half* __restrict__ gW1c, const __half* __restrict__ gW2c,
                const float* __restrict__ be1, const float* __restrict__ be2,
                const float* __restrict__ Wa,  const float* __restrict__ ba,
                const float* __restrict__ bc1, const float* __restrict__ bc2,
                const float* __restrict__ Wc3)
{
    extern __shared__ __align__(16) char sm[];
    float* sb1  = (float*)(sm + EOF_B1);
    float* sb2  = (float*)(sm + EOF_B2);
    float* shw  = (float*)(sm + EOF_HW);

    const int tid  = threadIdx.x;
    const int g    = tid >> 8;
    const int gtid = tid & 255;
    const int bar  = g + 1;
    const int mode = blockIdx.x & 1;
    const int cb   = blockIdx.x >> 1;

    char* grp = sm + EOF_GRP + g * GRP_SIZE;
    __half* Ps  = (__half*)(grp + GRP_PS);
    __half* Pd  = (__half*)(grp + GRP_PD);
    char*   fsm = grp + GRP_FSM;
    __half* act = (__half*)(grp + GRP_ACT);
    __half* act2 = (__half*)(grp + GRP_ACT2);
    int*    sidx = (int*)(grp + GRP_SIDX);
    float*  spart = (float*)(grp + GRP_SPART);

    const uint32_t fsmU = smem_u32(fsm), actU = smem_u32(act);
    const uint32_t w1sU = smem_u32(sm + EOF_W1S), w2U = smem_u32(sm + EOF_W2);

    const __half* gW1 = mode ? gW1c : gW1e;
    const __half* gW2 = mode ? gW2c : gW2e;
    const __half* gP1 = mode ? g_P1c : g_P1e;
    const __half* gP2 = mode ? g_P2c : g_P2e;
    const float*  b1  = mode ? bc1 : be1;
    const float*  b2  = mode ? bc2 : be2;
    const float*  hw  = mode ? Wc3 : Wa;
    const float   hb0 = mode ? 0.f : ba[0];

    for (int i = tid; i < 544; i += 512)
        ((float4*)(sm + EOF_W1S))[i] = ((const float4*)(gW1 + 256 * 136))[i];
    for (int i = tid; i < 2176; i += 512)
        ((float4*)(sm + EOF_W2))[i] = ((const float4*)gW2)[i];
    if (tid < 128) { sb1[tid] = b1[tid]; sb2[tid] = b2[tid]; shw[tid] = hw[tid]; }
    if (gtid < 64) {  // zero-pad fsm cols 20..31
        *(uint2*)(fsm + gtid * 80 + 40) = make_uint2(0, 0);
        *(uint2*)(fsm + gtid * 80 + 48) = make_uint2(0, 0);
        *(uint2*)(fsm + gtid * 80 + 56) = make_uint2(0, 0);
    }
    __syncthreads();

    const int t0 = cb * 2 + g;
    float pdx = 0.f, pdy = 0.f, pdz = 0.f, pr = 0.f;

    // ---------------- prologue: gather tile t0 ----------------
    if (gtid < 64) {
        const int e = t0 * 64 + gtid;
        const int s_ = src[e], d_ = dst[e];
        sidx[gtid] = s_; sidx[64 + gtid] = d_;
        pdx = coords[s_ * 3 + 0] - coords[d_ * 3 + 0];
        pdy = coords[s_ * 3 + 1] - coords[d_ * 3 + 1];
        pdz = coords[s_ * 3 + 2] - coords[d_ * 3 + 2];
        pr  = sqrtf(pdx * pdx + pdy * pdy + pdz * pdz);
        if (mode == 1) {
            float* sd = (float*)(grp + GRP_SD);
            sd[4 * gtid + 0] = pdx; sd[4 * gtid + 1] = pdy;
            sd[4 * gtid + 2] = pdz; sd[4 * gtid + 3] = pr;
        }
    }
    GBAR(bar);
    {
#pragma unroll
        for (int i = 0; i < 8; ++i) {
            const int idx = gtid + i * 256;
            const int el = idx >> 5, c = idx & 31;
            if (c < 16) {
                float4 v = *(const float4*)(gP1 + (size_t)sidx[el] * 128 + c * 8);
                *(float4*)((char*)Ps + el * 272 + c * 16) = v;
            } else {
                float4 v = *(const float4*)(gP2 + (size_t)sidx[64 + el] * 128 + (c - 16) * 8);
                *(float4*)((char*)Pd + el * 272 + (c - 16) * 16) = v;
            }
        }
        {
            const int row = gtid >> 2, part = gtid & 3;
            uint2 v = *(const uint2*)(g_a16 + (size_t)(t0 * 64 + row) * 16 + part * 4);
            *(uint2*)(fsm + row * 80 + 8 + part * 8) = v;
        }
        if (gtid < 64) {
            half2 d0 = __floats2half2_rn(pr, fabsf(pdx));
            half2 d1 = __floats2half2_rn(fabsf(pdy), fabsf(pdz));
            *(uint2*)(fsm + gtid * 80) = make_uint2(*(uint32_t*)&d0, *(uint32_t*)&d1);
        }
    }
    GBAR(bar);

    float acc[2][4][4];
    int buf = 0;
    const int lane = tid & 31;
    const int wvid = (tid >> 5) & 7;
    const int wm = wvid & 1, wn = wvid >> 1;

    // ---------------- persistent tile loop (3 barriers) ----------------
    for (int t = t0; t < NTILES64; t += NSTREAMS) {
        const int tn = t + NSTREAMS;
        const int nbuf = buf ^ 1;
        const bool pf = (tn < NTILES64);
        float4 rw[8];
        uint2  aR = make_uint2(0, 0);

        if (pf && gtid < 64) {
            const int e = tn * 64 + gtid;
            const int s_ = src[e], d_ = dst[e];
            sidx[nbuf * 128 + gtid] = s_;
            sidx[nbuf * 128 + 64 + gtid] = d_;
            pdx = coords[s_ * 3 + 0] - coords[d_ * 3 + 0];
            pdy = coords[s_ * 3 + 1] - coords[d_ * 3 + 1];
            pdz = coords[s_ * 3 + 2] - coords[d_ * 3 + 2];
            pr  = sqrtf(pdx * pdx + pdy * pdy + pdz * pdz);
            if (mode == 1) {
                float* sd = (float*)(grp + GRP_SD + nbuf * 1024);
                sd[4 * gtid + 0] = pdx; sd[4 * gtid + 1] = pdy;
                sd[4 * gtid + 2] = pdz; sd[4 * gtid + 3] = pr;
            }
        }

        if (pf) {
#pragma unroll
            for (int i = 0; i < 8; ++i) {
                const int idx = gtid + i * 256;
                const int el = idx >> 5, c = idx & 31;
                const int e = tn * 64 + el;
                rw[i] = (c < 16)
                    ? *(const float4*)(gP1 + (size_t)__ldg(src + e) * 128 + c * 8)
                    : *(const float4*)(gP2 + (size_t)__ldg(dst + e) * 128 + (c - 16) * 8);
            }
            aR = *(const uint2*)(g_a16 + (size_t)(tn * 64 + (gtid >> 2)) * 16 + (gtid & 3) * 4);
        }

        // G1small: [D|a] @ W1mid, K=32
        zero_acc(acc);
        gemm_g(fsmU, 40, w1sU, 2, acc);

        // E1: act = silu(acc + Ps + Pd + b1)
        epi_fuse_g(acc, Ps, Pd, sb1, act);
        GBAR(bar);   // (1)

        if (pf) {
#pragma unroll
            for (int i = 0; i < 8; ++i) {
                const int idx = gtid + i * 256;
                const int el = idx >> 5, c = idx & 31;
                if (c < 16) *(float4*)((char*)Ps + el * 272 + c * 16) = rw[i];
                else        *(float4*)((char*)Pd + el * 272 + (c - 16) * 16) = rw[i];
            }
            *(uint2*)(fsm + (gtid >> 2) * 80 + 8 + (gtid & 3) * 8) = aR;
            if (gtid < 64) {
                half2 d0 = __floats2half2_rn(pr, fabsf(pdx));
                half2 d1 = __floats2half2_rn(fabsf(pdy), fabsf(pdz));
                *(uint2*)(fsm + gtid * 80) = make_uint2(*(uint32_t*)&d0, *(uint32_t*)&d1);
            }
        }
        zero_acc(acc);
        gemm_g(actU, 136, w2U, 8, acc);

        // E2 fused: packed silu -> act2 (mode0 store) + partial head dot
        {
            float part[4] = {0.f, 0.f, 0.f, 0.f};
#pragma unroll
            for (int mt = 0; mt < 2; ++mt)
#pragma unroll
                for (int nt = 0; nt < 4; ++nt) {
                    const int row = wm * 32 + mt * 16 + (lane >> 2);
                    const int col = wn * 32 + nt * 8 + (lane & 3) * 2;
                    const float b0 = sb2[col], b1v = sb2[col + 1];
                    const float w0 = shw[col], w1 = shw[col + 1];
                    half2 r0 = silu2(acc[mt][nt][0] + b0, acc[mt][nt][1] + b1v);
                    half2 r1 = silu2(acc[mt][nt][2] + b0, acc[mt][nt][3] + b1v);
                    if (mode == 0) {
                        *(half2*)(act2 + row * 136 + col) = r0;
                        *(half2*)(act2 + (row + 8) * 136 + col) = r1;
                    }
                    float2 f0 = __half22float2(r0);
                    float2 f1 = __half22float2(r1);
                    part[mt * 2 + 0] = fmaf(f0.x, w0, fmaf(f0.y, w1, part[mt * 2 + 0]));
                    part[mt * 2 + 1] = fmaf(f1.x, w0, fmaf(f1.y, w1, part[mt * 2 + 1]));
                }
#pragma unroll
            for (int k = 0; k < 4; ++k) {
                part[k] += __shfl_xor_sync(0xFFFFFFFFu, part[k], 1);
                part[k] += __shfl_xor_sync(0xFFFFFFFFu, part[k], 2);
            }
            if ((lane & 3) == 0) {
                const int rsel = lane >> 2;
                spart[(wm * 32 +  0 + rsel) * 4 + wn] = part[0];
                spart[(wm * 32 +  8 + rsel) * 4 + wn] = part[1];
                spart[(wm * 32 + 16 + rsel) * 4 + wn] = part[2];
                spart[(wm * 32 + 24 + rsel) * 4 + wn] = part[3];
            }
        }
        GBAR(bar);   // (2)

        if (mode == 0) {
            const int row = gtid >> 2;
            const int q   = gtid & 3;
            const float dot = spart[row * 4 + 0] + spart[row * 4 + 1]
                            + spart[row * 4 + 2] + spart[row * 4 + 3];
            const float att = sigmoid_f(dot + hb0);
            float* hp = g_hagg + (size_t)sidx[buf * 128 + 64 + row] * 128 + q * 32;
            const half2* ar2 = (const half2*)(act2 + row * 136 + q * 32);
#pragma unroll
            for (int j = 0; j < 8; ++j) {
                float2 x0 = __half22float2(ar2[2 * j]);
                float2 x1 = __half22float2(ar2[2 * j + 1]);
                red_add_v4(hp + 4 * j, att * x0.x, att * x0.y, att * x1.x, att * x1.y);
            }
        } else {
            if (gtid < 64) {
                const float dot = spart[gtid * 4 + 0] + spart[gtid * 4 + 1]
                                + spart[gtid * 4 + 2] + spart[gtid * 4 + 3];
                const float* sd = (const float*)(grp + GRP_SD + buf * 1024);
                const float dx = sd[4 * gtid + 0], dy = sd[4 * gtid + 1];
                const float dz = sd[4 * gtid + 2], r  = sd[4 * gtid + 3];
                const float gg = dot / (r + 1.f);
                const int d_ = sidx[buf * 128 + 64 + gtid];
                atomicAdd(&g_xagg[d_ * 3 + 0], gg * dx);
                atomicAdd(&g_xagg[d_ * 3 + 1], gg * dy);
                atomicAdd(&g_xagg[d_ * 3 + 2], gg * dz);
            }
        }
        GBAR(bar);   // (3)
        buf = nbuf;
    }
}

// ---------------------------------------------------------------------------
// Persistent node kernel (packed silu in layer-1 epilogue)
// ---------------------------------------------------------------------------
#define NOF_W1   0
#define NOF_W2   69632
#define NOF_A    104448
#define NOF_ACT  172032
#define NOF_B    206848
#define NODE_SMEM 207872

__global__ void __launch_bounds__(512, 1)
node_kernel(const float* __restrict__ hmat, const float* __restrict__ coords,
            const float* __restrict__ bn1, const float* __restrict__ bn2,
            float* __restrict__ out)
{
    extern __shared__ __align__(16) char sm[];
    __half* sW1 = (__half*)(sm + NOF_W1);
    __half* sW2 = (__half*)(sm + NOF_W2);
    char*   aB  = sm + NOF_A;
    __half* act = (__half*)(sm + NOF_ACT);
    float* sb1  = (float*)(sm + NOF_B);
    float* sb2  = sb1 + 128;

    const uint32_t aU = smem_u32(aB), w1U = smem_u32(sW1);
    const uint32_t w2U = smem_u32(sW2), actU = smem_u32(act);
    const int tid = threadIdx.x;

    for (int i = tid; i < 4352; i += 512) ((float4*)sW1)[i] = ((const float4*)g_Wn1)[i];
    for (int i = tid; i < 2176; i += 512) ((float4*)sW2)[i] = ((const float4*)g_Wn2)[i];
    if (tid < 128) { sb1[tid] = bn1[tid]; sb2[tid] = bn2[tid]; }
    __syncthreads();

    const int lane = tid & 31;
    const int wid  = tid >> 5;
    const int wm = wid & 3, wn = wid >> 2;
    float acc[2][4][4];

    for (int t = blockIdx.x; t < NODE_TILES; t += 148) {
        const int n0 = t * 128;

#pragma unroll
        for (int i = 0; i < 4; ++i) {
            const int idx = tid + i * 512;
            const int el = idx >> 4, c = idx & 15;
            const int n = n0 + el;
            float4 v = make_float4(0.f, 0.f, 0.f, 0.f);
            if (n < N_NODES) v = *(const float4*)(g_h16 + (size_t)n * 128 + c * 8);
            *(float4*)(aB + el * 528 + c * 16) = v;
        }
#pragma unroll
        for (int i = 0; i < 8; ++i) {
            const int idx = tid + i * 512;
            const int el = idx >> 5, c = idx & 31;
            const int n = n0 + el;
            float4 v = make_float4(0.f, 0.f, 0.f, 0.f);
            if (n < N_NODES) v = ((const float4*)g_hagg)[(size_t)n * 32 + c];
            half2 h0 = __floats2half2_rn(v.x, v.y);
            half2 h1 = __floats2half2_rn(v.z, v.w);
            *(uint2*)(aB + el * 528 + 256 + c * 8) =
                make_uint2(*(uint32_t*)&h0, *(uint32_t*)&h1);
        }
        __syncthreads();

        zero_acc32(acc);
        gemm512(aU, 264, w1U, 16, acc);
        __syncthreads();
        {
#pragma unroll
            for (int mt = 0; mt < 2; ++mt)
#pragma unroll
                for (int nt = 0; nt < 4; ++nt) {
                    const int row = wm * 32 + mt * 16 + (lane >> 2);
                    const int col = wn * 32 + nt * 8 + (lane & 3) * 2;
                    const float b0 = sb1[col], b1v = sb1[col + 1];
                    *(half2*)(act + row * 136 + col) =
                        silu2(acc[mt][nt][0] + b0, acc[mt][nt][1] + b1v);
                    *(half2*)(act + (row + 8) * 136 + col) =
                        silu2(acc[mt][nt][2] + b0, acc[mt][nt][3] + b1v);
                }
        }
        __syncthreads();

        zero_acc32(acc);
        gemm512(actU, 136, w2U, 8, acc);

#pragma unroll
        for (int mt = 0; mt < 2; ++mt)
#pragma unroll
            for (int nt = 0; nt < 4; ++nt) {
                const int row = wm * 32 + mt * 16 + (lane >> 2);
                const int col = wn * 32 + nt * 8 + (lane & 3) * 2;
                const float b0 = sb2[col], b1v = sb2[col + 1];
                int n = n0 + row;
                if (n < N_NODES) {
                    float2 hv = *(const float2*)(hmat + (size_t)n * 128 + col);
                    *(float2*)(out + (size_t)n * 128 + col) =
                        make_float2(hv.x + acc[mt][nt][0] + b0, hv.y + acc[mt][nt][1] + b1v);
                }
                n = n0 + row + 8;
                if (n < N_NODES) {
                    float2 hv = *(const float2*)(hmat + (size_t)n * 128 + col);
                    *(float2*)(out + (size_t)n * 128 + col) =
                        make_float2(hv.x + acc[mt][nt][2] + b0, hv.y + acc[mt][nt][3] + b1v);
                }
            }

        if (tid < 128) {
            const int n = n0 + tid;
            if (n < N_NODES) {
                const size_t base = (size_t)N_NODES * 128;
                out[base + n * 3 + 0] = coords[n * 3 + 0] + g_xagg[n * 3 + 0];
                out[base + n * 3 + 1] = coords[n * 3 + 1] + g_xagg[n * 3 + 1];
                out[base + n * 3 + 2] = coords[n * 3 + 2] + g_xagg[n * 3 + 2];
            }
        }
        __syncthreads();
    }
}

// ---------------------------------------------------------------------------
extern "C" void kernel_launch(void* const* d_in, const int* in_sizes, int n_in,
                              void* d_out, int out_size)
{
    const float* h      = (const float*)d_in[0];
    const float* coords = (const float*)d_in[1];
    const float* a      = (const float*)d_in[2];
    const int*   src    = (const int*)d_in[3];
    const int*   dst    = (const int*)d_in[4];
    const float* We1 = (const float*)d_in[5];
    const float* be1 = (const float*)d_in[6];
    const float* We2 = (const float*)d_in[7];
    const float* be2 = (const float*)d_in[8];
    const float* Wa  = (const float*)d_in[9];
    const float* ba  = (const float*)d_in[10];
    const float* Wn1 = (const float*)d_in[11];
    const float* bn1 = (const float*)d_in[12];
    const float* Wn2 = (const float*)d_in[13];
    const float* bn2 = (const float*)d_in[14];
    const float* Wc1 = (const float*)d_in[15];
    const float* bc1 = (const float*)d_in[16];
    const float* Wc2 = (const float*)d_in[17];
    const float* bc2 = (const float*)d_in[18];
    const float* Wc3 = (const float*)d_in[19];
    float* out = (float*)d_out;

    __half *dW1e, *dW1c, *dWe2, *dWc2;
    cudaGetSymbolAddress((void**)&dW1e, g_W1e);
    cudaGetSymbolAddress((void**)&dW1c, g_W1c);
    cudaGetSymbolAddress((void**)&dWe2, g_We2);
    cudaGetSymbolAddress((void**)&dWc2, g_Wc2);

    cudaFuncSetAttribute(precompute_kernel, cudaFuncAttributeMaxDynamicSharedMemorySize, PC_SMEM);
    cudaFuncSetAttribute(edge_fat_kernel, cudaFuncAttributeMaxDynamicSharedMemorySize, EDGE_SMEM);
    cudaFuncSetAttribute(node_kernel, cudaFuncAttributeMaxDynamicSharedMemorySize, NODE_SMEM);

    prep_kernel<<<1024, 256>>>(h, a, We1, Wc1, We2, Wc2, Wn1, Wn2);
    precompute_kernel<<<148, 512, PC_SMEM>>>();
    edge_fat_kernel<<<148, 512, EDGE_SMEM>>>(
        coords, src, dst, dW1e, dWe2, dW1c, dWc2,
        be1, be2, Wa, ba, bc1, bc2, Wc3);
    node_kernel<<<148, 512, NODE_SMEM>>>(h, coords, bn1, bn2, out);
}

// round 15
// speedup vs baseline: 1.6513x; 1.6513x over previous
#include <cuda_runtime.h>
#include <cuda_fp16.h>
#include <cstdint>
#include <math.h>

#define N_NODES 50000
#define E_EDGES 800000
#define H 128
#define MF 276
#define NTILES64 (E_EDGES / 64)             // 12500 64-edge tiles
#define NSTREAMS 148                        // 74 CTAs/mode x 2 groups
#define NODE_TILES ((N_NODES + 127) / 128)  // 391

// ---------------------------------------------------------------------------
__device__ float  g_hagg[N_NODES * H];
__device__ float  g_xagg[N_NODES * 3];
__device__ __half g_h16[N_NODES * H];
__device__ __half g_a16[E_EDGES * 16];
__device__ __half g_W1e[288 * 136];
__device__ __half g_W1c[288 * 136];
__device__ __half g_We2[128 * 136];
__device__ __half g_Wc2[128 * 136];
__device__ __half g_Wn1[256 * 136];
__device__ __half g_Wn2[128 * 136];
__device__ __half g_P1e[N_NODES * H];   // h@We1_top + be1 (bias folded)
__device__ __half g_P2e[N_NODES * H];
__device__ __half g_P1c[N_NODES * H];   // h@Wc1_top + bc1
__device__ __half g_P2c[N_NODES * H];

__device__ __forceinline__ uint32_t smem_u32(const void* p) {
    uint32_t a;
    asm("{ .reg .u64 t; cvta.to.shared.u64 t, %1; cvt.u32.u64 %0, t; }"
        : "=r"(a) : "l"(p));
    return a;
}
__device__ __forceinline__ float tanh_f(float x) {
    float y;
    asm("tanh.approx.f32 %0, %1;" : "=f"(y) : "f"(x));
    return y;
}
__device__ __forceinline__ float silu_f(float v) {
    const float hv = 0.5f * v;
    return fmaf(hv, tanh_f(hv), hv);
}
__device__ __forceinline__ float sigmoid_f(float x) {
    return fmaf(0.5f, tanh_f(0.5f * x), 0.5f);
}
__device__ __forceinline__ void red_add_v4(float* p, float a, float b, float c, float d) {
    asm volatile("red.global.add.v4.f32 [%0], {%1,%2,%3,%4};"
        :: "l"(p), "f"(a), "f"(b), "f"(c), "f"(d) : "memory");
}
__device__ __forceinline__ uint4 hadd2x4(uint4 a, uint4 b) {
    uint4 r;
    half2* ra = (half2*)&a; half2* rb = (half2*)&b; half2* rr = (half2*)&r;
#pragma unroll
    for (int i = 0; i < 4; ++i) rr[i] = __hadd2(ra[i], rb[i]);
    return r;
}
#define GBAR(id) asm volatile("bar.sync %0, 256;" :: "r"(id) : "memory")

// ---------------------------------------------------------------------------
// Group GEMM (fp32 acc): 8 warps in 2(M)x4(N); C tile 64x128.
// ---------------------------------------------------------------------------
__device__ __forceinline__ void zero_acc(float (&acc)[2][4][4]) {
#pragma unroll
    for (int mt = 0; mt < 2; ++mt)
#pragma unroll
        for (int nt = 0; nt < 4; ++nt)
#pragma unroll
            for (int i = 0; i < 4; ++i) acc[mt][nt][i] = 0.f;
}

__device__ __forceinline__ void gemm_g(uint32_t aBase, int aStride,
                                       uint32_t bBase, int ksteps,
                                       float (&acc)[2][4][4])
{
    const int lane = threadIdx.x & 31;
    const int wid  = (threadIdx.x >> 5) & 7;
    const int wm   = wid & 1;
    const int wn   = wid >> 1;
    const int arow = wm * 32 + (lane & 15);
    const int acoff = (lane & 16) ? 8 : 0;
    const int brow = lane & 15;
    const int bcol = wn * 32 + ((lane & 16) ? 8 : 0);

    for (int ks = 0; ks < ksteps; ++ks) {
        const int k0 = ks * 16;
        uint32_t a[2][4];
#pragma unroll
        for (int mt = 0; mt < 2; ++mt) {
            uint32_t ad = aBase + (uint32_t)(((arow + mt * 16) * aStride + k0 + acoff) * 2);
            asm volatile("ldmatrix.sync.aligned.m8n8.x4.shared.b16 {%0,%1,%2,%3}, [%4];"
                : "=r"(a[mt][0]), "=r"(a[mt][1]), "=r"(a[mt][2]), "=r"(a[mt][3]) : "r"(ad));
        }
        uint32_t b[4][2];
#pragma unroll
        for (int nt2 = 0; nt2 < 2; ++nt2) {
            uint32_t bd = bBase + (uint32_t)(((k0 + brow) * 136 + bcol + nt2 * 16) * 2);
            asm volatile("ldmatrix.sync.aligned.m8n8.x4.trans.shared.b16 {%0,%1,%2,%3}, [%4];"
                : "=r"(b[2 * nt2][0]), "=r"(b[2 * nt2][1]),
                  "=r"(b[2 * nt2 + 1][0]), "=r"(b[2 * nt2 + 1][1]) : "r"(bd));
        }
#pragma unroll
        for (int mt = 0; mt < 2; ++mt)
#pragma unroll
            for (int nt = 0; nt < 4; ++nt)
                asm volatile("mma.sync.aligned.m16n8k16.row.col.f32.f16.f16.f32 "
                    "{%0,%1,%2,%3}, {%4,%5,%6,%7}, {%8,%9}, {%0,%1,%2,%3};"
                    : "+f"(acc[mt][nt][0]), "+f"(acc[mt][nt][1]),
                      "+f"(acc[mt][nt][2]), "+f"(acc[mt][nt][3])
                    : "r"(a[mt][0]), "r"(a[mt][1]), "r"(a[mt][2]), "r"(a[mt][3]),
                      "r"(b[nt][0]), "r"(b[nt][1]));
    }
}

// E1: act = silu(acc + Psum)   (bias folded into Psum)
__device__ __forceinline__ void epi_fuse_g(const float (&acc)[2][4][4],
                                           const __half* __restrict__ Psum,
                                           __half* act)
{
    const int lane = threadIdx.x & 31;
    const int wid  = (threadIdx.x >> 5) & 7;
    const int wm = wid & 1, wn = wid >> 1;
#pragma unroll
    for (int mt = 0; mt < 2; ++mt)
#pragma unroll
        for (int nt = 0; nt < 4; ++nt) {
            const int row = wm * 32 + mt * 16 + (lane >> 2);
            const int col = wn * 32 + nt * 8 + (lane & 3) * 2;
#pragma unroll
            for (int rr = 0; rr < 2; ++rr) {
                const int r = row + rr * 8;
                float2 ps = __half22float2(*(const half2*)(Psum + r * 136 + col));
                float v0 = acc[mt][nt][2 * rr + 0] + ps.x;
                float v1 = acc[mt][nt][2 * rr + 1] + ps.y;
                *(half2*)(act + r * 136 + col) =
                    __floats2half2_rn(silu_f(v0), silu_f(v1));
            }
        }
}

// ---------------------------------------------------------------------------
// 512-thread GEMM (16 warps 4x4), C tile 128x128
// ---------------------------------------------------------------------------
__device__ __forceinline__ void zero_acc32(float (&acc)[2][4][4]) { zero_acc(acc); }

__device__ __forceinline__ void gemm512(uint32_t aBase, int aStride,
                                        uint32_t bBase, int ksteps,
                                        float (&acc)[2][4][4])
{
    const int lane = threadIdx.x & 31;
    const int wid  = threadIdx.x >> 5;
    const int wm   = wid & 3;
    const int wn   = wid >> 2;
    const int arow = wm * 32 + (lane & 15);
    const int acoff = (lane & 16) ? 8 : 0;
    const int brow = lane & 15;
    const int bcol = wn * 32 + ((lane & 16) ? 8 : 0);

    for (int ks = 0; ks < ksteps; ++ks) {
        const int k0 = ks * 16;
        uint32_t a[2][4];
#pragma unroll
        for (int mt = 0; mt < 2; ++mt) {
            uint32_t ad = aBase + (uint32_t)(((arow + mt * 16) * aStride + k0 + acoff) * 2);
            asm volatile("ldmatrix.sync.aligned.m8n8.x4.shared.b16 {%0,%1,%2,%3}, [%4];"
                : "=r"(a[mt][0]), "=r"(a[mt][1]), "=r"(a[mt][2]), "=r"(a[mt][3]) : "r"(ad));
        }
        uint32_t b[4][2];
#pragma unroll
        for (int nt2 = 0; nt2 < 2; ++nt2) {
            uint32_t bd = bBase + (uint32_t)(((k0 + brow) * 136 + bcol + nt2 * 16) * 2);
            asm volatile("ldmatrix.sync.aligned.m8n8.x4.trans.shared.b16 {%0,%1,%2,%3}, [%4];"
                : "=r"(b[2 * nt2][0]), "=r"(b[2 * nt2][1]),
                  "=r"(b[2 * nt2 + 1][0]), "=r"(b[2 * nt2 + 1][1]) : "r"(bd));
        }
#pragma unroll
        for (int mt = 0; mt < 2; ++mt)
#pragma unroll
            for (int nt = 0; nt < 4; ++nt)
                asm volatile("mma.sync.aligned.m16n8k16.row.col.f32.f16.f16.f32 "
                    "{%0,%1,%2,%3}, {%4,%5,%6,%7}, {%8,%9}, {%0,%1,%2,%3};"
                    : "+f"(acc[mt][nt][0]), "+f"(acc[mt][nt][1]),
                      "+f"(acc[mt][nt][2]), "+f"(acc[mt][nt][3])
                    : "r"(a[mt][0]), "r"(a[mt][1]), "r"(a[mt][2]), "r"(a[mt][3]),
                      "r"(b[nt][0]), "r"(b[nt][1]));
    }
}

// ---------------------------------------------------------------------------
__global__ void prep_kernel(const float* __restrict__ hmat, const float* __restrict__ amat,
                            const float* __restrict__ We1, const float* __restrict__ Wc1,
                            const float* __restrict__ We2, const float* __restrict__ Wc2,
                            const float* __restrict__ Wn1, const float* __restrict__ Wn2)
{
    const int stride = gridDim.x * blockDim.x;
    const int tid0 = blockIdx.x * blockDim.x + threadIdx.x;
    const __half hz = __float2half_rn(0.f);
    for (int i = tid0; i < N_NODES * H / 2; i += stride) {
        float2 v = ((const float2*)hmat)[i];
        ((half2*)g_h16)[i] = __floats2half2_rn(v.x, v.y);
    }
    for (int i = tid0; i < E_EDGES * 8; i += stride) {
        float2 v = ((const float2*)amat)[i];
        ((half2*)g_a16)[i] = __floats2half2_rn(v.x, v.y);
    }
    for (int i = tid0; i < 288 * 136; i += stride) {
        int k = i / 136, n = i % 136;
        bool ok = (k < MF) && (n < 128);
        g_W1e[i] = ok ? __float2half_rn(We1[k * 128 + n]) : hz;
        g_W1c[i] = ok ? __float2half_rn(Wc1[k * 128 + n]) : hz;
    }
    for (int i = tid0; i < 256 * 136; i += stride) {
        int k = i / 136, n = i % 136;
        g_Wn1[i] = (n < 128) ? __float2half_rn(Wn1[k * 128 + n]) : hz;
    }
    for (int i = tid0; i < 128 * 136; i += stride) {
        int k = i / 136, n = i % 136;
        bool ok = (n < 128);
        g_We2[i] = ok ? __float2half_rn(We2[k * 128 + n]) : hz;
        g_Wc2[i] = ok ? __float2half_rn(Wc2[k * 128 + n]) : hz;
        g_Wn2[i] = ok ? __float2half_rn(Wn2[k * 128 + n]) : hz;
    }
    for (int i = tid0; i < N_NODES * H; i += stride) g_hagg[i] = 0.f;
    for (int i = tid0; i < N_NODES * 3; i += stride) g_xagg[i] = 0.f;
}

// ---------------------------------------------------------------------------
// precompute: P1e=h@We1_top+be1, P2e=h@We1_bot, P1c=h@Wc1_top+bc1, P2c=h@Wc1_bot
// ---------------------------------------------------------------------------
#define PC_A     0
#define PC_W     34816
#define PC_SMEM  174080

__global__ void __launch_bounds__(512, 1)
precompute_kernel(const float* __restrict__ be1, const float* __restrict__ bc1)
{
    extern __shared__ __align__(16) char sm[];
    __half* A  = (__half*)(sm + PC_A);
    const uint32_t aU = smem_u32(A);
    const uint32_t wU = smem_u32(sm + PC_W);
    const int tid = threadIdx.x;

    for (int i = tid; i < 4352; i += 512)
        ((float4*)(sm + PC_W))[i] = ((const float4*)g_W1e)[i];
    for (int i = tid; i < 4352; i += 512)
        ((float4*)(sm + PC_W + 69632))[i] = ((const float4*)g_W1c)[i];
    __syncthreads();

    const int lane = tid & 31;
    const int wid  = tid >> 5;
    const int wm = wid & 3, wn = wid >> 2;
    __half* gP[4] = { g_P1e, g_P2e, g_P1c, g_P2c };
    float acc[2][4][4];

    for (int t = blockIdx.x; t < NODE_TILES; t += 148) {
        const int n0 = t * 128;
#pragma unroll
        for (int i = 0; i < 4; ++i) {
            const int idx = tid + i * 512;
            const int el = idx >> 4, c = idx & 15;
            const int n = n0 + el;
            float4 v = make_float4(0.f, 0.f, 0.f, 0.f);
            if (n < N_NODES) v = *(const float4*)(g_h16 + (size_t)n * 128 + c * 8);
            *(float4*)((char*)A + el * 272 + c * 16) = v;
        }
        __syncthreads();

#pragma unroll
        for (int j = 0; j < 4; ++j) {
            zero_acc32(acc);
            gemm512(aU, 136, wU + j * 34816, 8, acc);
            __half* P = gP[j];
            const float* bias = (j == 0) ? be1 : ((j == 2) ? bc1 : nullptr);
#pragma unroll
            for (int mt = 0; mt < 2; ++mt)
#pragma unroll
                for (int nt = 0; nt < 4; ++nt) {
                    const int row = wm * 32 + mt * 16 + (lane >> 2);
                    const int col = wn * 32 + nt * 8 + (lane & 3) * 2;
                    const float b0 = bias ? bias[col] : 0.f;
                    const float b1 = bias ? bias[col + 1] : 0.f;
                    int n = n0 + row;
                    if (n < N_NODES)
                        *(half2*)(P + (size_t)n * 128 + col) =
                            __floats2half2_rn(acc[mt][nt][0] + b0, acc[mt][nt][1] + b1);
                    n = n0 + row + 8;
                    if (n < N_NODES)
                        *(half2*)(P + (size_t)n * 128 + col) =
                            __floats2half2_rn(acc[mt][nt][2] + b0, acc[mt][nt][3] + b1);
                }
        }
        __syncthreads();
    }
}

// ---------------------------------------------------------------------------
// Fat persistent edge kernel: factorized layer-1, fused Psum, 3 barriers/tile.
// ---------------------------------------------------------------------------
#define EOF_W1S   0           // 32 x 136 h = 8704
#define EOF_W2    8704        // 34816
#define EOF_B2    43520
#define EOF_HW    44032
#define EOF_GRP   44544
#define GRP_PS    0           // Psum: 64 x 136 h = 17408
#define GRP_FSM   17408       // 64 x 40 h = 5120
#define GRP_ACT   22528       // 17408
#define GRP_ACT2  39936       // 17408
#define GRP_SD    57344       // 2 x 1024
#define GRP_SIDX  59392       // 2 x 512
#define GRP_SPART 60416       // 64 x 4 f = 1024
#define GRP_SIZE  61440
#define EDGE_SMEM (EOF_GRP + 2 * GRP_SIZE)   // 167424

__global__ void __launch_bounds__(512, 1)
edge_fat_kernel(const float* __restrict__ coords,
                const int* __restrict__ src, const int* __restrict__ dst,
                const __half* __restrict__ gW1e, const __half* __restrict__ gW2e,
                const __half* __restrict__ gW1c, const __half* __restrict__ gW2c,
                const float* __restrict__ be2,
                const float* __restrict__ Wa,  const float* __restrict__ ba,
                const float* __restrict__ bc2,
                const float* __restrict__ Wc3)
{
    extern __shared__ __align__(16) char sm[];
    float* sb2  = (float*)(sm + EOF_B2);
    float* shw  = (float*)(sm + EOF_HW);

    const int tid  = threadIdx.x;
    const int g    = tid >> 8;
    const int gtid = tid & 255;
    const int bar  = g + 1;
    const int mode = blockIdx.x & 1;
    const int cb   = blockIdx.x >> 1;

    char* grp = sm + EOF_GRP + g * GRP_SIZE;
    __half* Ps  = (__half*)(grp + GRP_PS);      // Psum
    char*   fsm = grp + GRP_FSM;
    __half* act = (__half*)(grp + GRP_ACT);
    __half* act2 = (__half*)(grp + GRP_ACT2);
    int*    sidx = (int*)(grp + GRP_SIDX);
    float*  spart = (float*)(grp + GRP_SPART);

    const uint32_t fsmU = smem_u32(fsm), actU = smem_u32(act);
    const uint32_t w1sU = smem_u32(sm + EOF_W1S), w2U = smem_u32(sm + EOF_W2);

    const __half* gW1 = mode ? gW1c : gW1e;
    const __half* gW2 = mode ? gW2c : gW2e;
    const __half* gP1 = mode ? g_P1c : g_P1e;
    const __half* gP2 = mode ? g_P2c : g_P2e;
    const float*  b2  = mode ? bc2 : be2;
    const float*  hw  = mode ? Wc3 : Wa;
    const float   hb0 = mode ? 0.f : ba[0];

    for (int i = tid; i < 544; i += 512)
        ((float4*)(sm + EOF_W1S))[i] = ((const float4*)(gW1 + 256 * 136))[i];
    for (int i = tid; i < 2176; i += 512)
        ((float4*)(sm + EOF_W2))[i] = ((const float4*)gW2)[i];
    if (tid < 128) { sb2[tid] = b2[tid]; shw[tid] = hw[tid]; }
    if (gtid < 64) {  // zero-pad fsm cols 20..31
        *(uint2*)(fsm + gtid * 80 + 40) = make_uint2(0, 0);
        *(uint2*)(fsm + gtid * 80 + 48) = make_uint2(0, 0);
        *(uint2*)(fsm + gtid * 80 + 56) = make_uint2(0, 0);
    }
    __syncthreads();

    const int t0 = cb * 2 + g;
    float pdx = 0.f, pdy = 0.f, pdz = 0.f, pr = 0.f;

    // ---------------- prologue: gather tile t0 ----------------
    if (gtid < 64) {
        const int e = t0 * 64 + gtid;
        const int s_ = src[e], d_ = dst[e];
        sidx[gtid] = s_; sidx[64 + gtid] = d_;
        pdx = coords[s_ * 3 + 0] - coords[d_ * 3 + 0];
        pdy = coords[s_ * 3 + 1] - coords[d_ * 3 + 1];
        pdz = coords[s_ * 3 + 2] - coords[d_ * 3 + 2];
        pr  = sqrtf(pdx * pdx + pdy * pdy + pdz * pdz);
        if (mode == 1) {
            float* sd = (float*)(grp + GRP_SD);
            sd[4 * gtid + 0] = pdx; sd[4 * gtid + 1] = pdy;
            sd[4 * gtid + 2] = pdz; sd[4 * gtid + 3] = pr;
        }
    }
    GBAR(bar);
    {
#pragma unroll
        for (int i = 0; i < 4; ++i) {
            const int idx = gtid + i * 256;
            const int el = idx >> 4, c = idx & 15;
            uint4 p1 = *(const uint4*)(gP1 + (size_t)sidx[el] * 128 + c * 8);
            uint4 p2 = *(const uint4*)(gP2 + (size_t)sidx[64 + el] * 128 + c * 8);
            *(uint4*)((char*)Ps + el * 272 + c * 16) = hadd2x4(p1, p2);
        }
        {
            const int row = gtid >> 2, part = gtid & 3;
            uint2 v = *(const uint2*)(g_a16 + (size_t)(t0 * 64 + row) * 16 + part * 4);
            *(uint2*)(fsm + row * 80 + 8 + part * 8) = v;
        }
        if (gtid < 64) {
            half2 d0 = __floats2half2_rn(pr, fabsf(pdx));
            half2 d1 = __floats2half2_rn(fabsf(pdy), fabsf(pdz));
            *(uint2*)(fsm + gtid * 80) = make_uint2(*(uint32_t*)&d0, *(uint32_t*)&d1);
        }
    }
    GBAR(bar);

    float acc[2][4][4];
    int buf = 0;
    const int lane = tid & 31;
    const int wvid = (tid >> 5) & 7;
    const int wm = wvid & 1, wn = wvid >> 1;

    // ---------------- persistent tile loop (3 barriers) ----------------
    for (int t = t0; t < NTILES64; t += NSTREAMS) {
        const int tn = t + NSTREAMS;
        const int nbuf = buf ^ 1;
        const bool pf = (tn < NTILES64);
        uint4 rw[4];
        uint2 aR = make_uint2(0, 0);

        if (pf && gtid < 64) {
            const int e = tn * 64 + gtid;
            const int s_ = src[e], d_ = dst[e];
            sidx[nbuf * 128 + gtid] = s_;
            sidx[nbuf * 128 + 64 + gtid] = d_;
            pdx = coords[s_ * 3 + 0] - coords[d_ * 3 + 0];
            pdy = coords[s_ * 3 + 1] - coords[d_ * 3 + 1];
            pdz = coords[s_ * 3 + 2] - coords[d_ * 3 + 2];
            pr  = sqrtf(pdx * pdx + pdy * pdy + pdz * pdz);
            if (mode == 1) {
                float* sd = (float*)(grp + GRP_SD + nbuf * 1024);
                sd[4 * gtid + 0] = pdx; sd[4 * gtid + 1] = pdy;
                sd[4 * gtid + 2] = pdz; sd[4 * gtid + 3] = pr;
            }
        }

        // gather for tn: Psum in registers (indices straight from global)
        if (pf) {
#pragma unroll
            for (int i = 0; i < 4; ++i) {
                const int idx = gtid + i * 256;
                const int el = idx >> 4, c = idx & 15;
                const int e = tn * 64 + el;
                uint4 p1 = *(const uint4*)(gP1 + (size_t)__ldg(src + e) * 128 + c * 8);
                uint4 p2 = *(const uint4*)(gP2 + (size_t)__ldg(dst + e) * 128 + c * 8);
                rw[i] = hadd2x4(p1, p2);
            }
            aR = *(const uint2*)(g_a16 + (size_t)(tn * 64 + (gtid >> 2)) * 16 + (gtid & 3) * 4);
        }

        // G1small: [D|a] @ W1mid, K=32
        zero_acc(acc);
        gemm_g(fsmU, 40, w1sU, 2, acc);

        // E1: act = silu(acc + Psum)
        epi_fuse_g(acc, Ps, act);
        GBAR(bar);   // (1) Psum/fsm reads done; act visible

        // commit tn data, then G2
        if (pf) {
#pragma unroll
            for (int i = 0; i < 4; ++i) {
                const int idx = gtid + i * 256;
                const int el = idx >> 4, c = idx & 15;
                *(uint4*)((char*)Ps + el * 272 + c * 16) = rw[i];
            }
            *(uint2*)(fsm + (gtid >> 2) * 80 + 8 + (gtid & 3) * 8) = aR;
            if (gtid < 64) {
                half2 d0 = __floats2half2_rn(pr, fabsf(pdx));
                half2 d1 = __floats2half2_rn(fabsf(pdy), fabsf(pdz));
                *(uint2*)(fsm + gtid * 80) = make_uint2(*(uint32_t*)&d0, *(uint32_t*)&d1);
            }
        }
        zero_acc(acc);
        gemm_g(actU, 136, w2U, 8, acc);

        // E2 fused: silu -> act2 (mode0 store) + partial head dot
        {
            float part[4] = {0.f, 0.f, 0.f, 0.f};
#pragma unroll
            for (int mt = 0; mt < 2; ++mt)
#pragma unroll
                for (int nt = 0; nt < 4; ++nt) {
                    const int row = wm * 32 + mt * 16 + (lane >> 2);
                    const int col = wn * 32 + nt * 8 + (lane & 3) * 2;
                    const float b0 = sb2[col], b1v = sb2[col + 1];
                    const float w0 = shw[col], w1 = shw[col + 1];
                    const float v0 = silu_f(acc[mt][nt][0] + b0);
                    const float v1 = silu_f(acc[mt][nt][1] + b1v);
                    const float v2 = silu_f(acc[mt][nt][2] + b0);
                    const float v3 = silu_f(acc[mt][nt][3] + b1v);
                    if (mode == 0) {
                        *(half2*)(act2 + row * 136 + col) = __floats2half2_rn(v0, v1);
                        *(half2*)(act2 + (row + 8) * 136 + col) = __floats2half2_rn(v2, v3);
                    }
                    part[mt * 2 + 0] = fmaf(v0, w0, fmaf(v1, w1, part[mt * 2 + 0]));
                    part[mt * 2 + 1] = fmaf(v2, w0, fmaf(v3, w1, part[mt * 2 + 1]));
                }
#pragma unroll
            for (int k = 0; k < 4; ++k) {
                part[k] += __shfl_xor_sync(0xFFFFFFFFu, part[k], 1);
                part[k] += __shfl_xor_sync(0xFFFFFFFFu, part[k], 2);
            }
            if ((lane & 3) == 0) {
                const int rsel = lane >> 2;
                spart[(wm * 32 +  0 + rsel) * 4 + wn] = part[0];
                spart[(wm * 32 +  8 + rsel) * 4 + wn] = part[1];
                spart[(wm * 32 + 16 + rsel) * 4 + wn] = part[2];
                spart[(wm * 32 + 24 + rsel) * 4 + wn] = part[3];
            }
        }
        GBAR(bar);   // (2) act2 + spart visible

        if (mode == 0) {
            const int row = gtid >> 2;
            const int q   = gtid & 3;
            const float dot = spart[row * 4 + 0] + spart[row * 4 + 1]
                            + spart[row * 4 + 2] + spart[row * 4 + 3];
            const float att = sigmoid_f(dot + hb0);
            float* hp = g_hagg + (size_t)sidx[buf * 128 + 64 + row] * 128 + q * 32;
            const half2* ar2 = (const half2*)(act2 + row * 136 + q * 32);
#pragma unroll
            for (int j = 0; j < 8; ++j) {
                float2 x0 = __half22float2(ar2[2 * j]);
                float2 x1 = __half22float2(ar2[2 * j + 1]);
                red_add_v4(hp + 4 * j, att * x0.x, att * x0.y, att * x1.x, att * x1.y);
            }
        } else {
            if (gtid < 64) {
                const float dot = spart[gtid * 4 + 0] + spart[gtid * 4 + 1]
                                + spart[gtid * 4 + 2] + spart[gtid * 4 + 3];
                const float* sd = (const float*)(grp + GRP_SD + buf * 1024);
                const float dx = sd[4 * gtid + 0], dy = sd[4 * gtid + 1];
                const float dz = sd[4 * gtid + 2], r  = sd[4 * gtid + 3];
                const float gg = dot / (r + 1.f);
                const int d_ = sidx[buf * 128 + 64 + gtid];
                atomicAdd(&g_xagg[d_ * 3 + 0], gg * dx);
                atomicAdd(&g_xagg[d_ * 3 + 1], gg * dy);
                atomicAdd(&g_xagg[d_ * 3 + 2], gg * dz);
            }
        }
        GBAR(bar);   // (3) end of tile
        buf = nbuf;
    }
}

// ---------------------------------------------------------------------------
// Persistent node kernel (f32 tanh silu)
// ---------------------------------------------------------------------------
#define NOF_W1   0
#define NOF_W2   69632
#define NOF_A    104448
#define NOF_ACT  172032
#define NOF_B    206848
#define NODE_SMEM 207872

__global__ void __launch_bounds__(512, 1)
node_kernel(const float* __restrict__ hmat, const float* __restrict__ coords,
            const float* __restrict__ bn1, const float* __restrict__ bn2,
            float* __restrict__ out)
{
    extern __shared__ __align__(16) char sm[];
    __half* sW1 = (__half*)(sm + NOF_W1);
    __half* sW2 = (__half*)(sm + NOF_W2);
    char*   aB  = sm + NOF_A;
    __half* act = (__half*)(sm + NOF_ACT);
    float* sb1  = (float*)(sm + NOF_B);
    float* sb2  = sb1 + 128;

    const uint32_t aU = smem_u32(aB), w1U = smem_u32(sW1);
    const uint32_t w2U = smem_u32(sW2), actU = smem_u32(act);
    const int tid = threadIdx.x;

    for (int i = tid; i < 4352; i += 512) ((float4*)sW1)[i] = ((const float4*)g_Wn1)[i];
    for (int i = tid; i < 2176; i += 512) ((float4*)sW2)[i] = ((const float4*)g_Wn2)[i];
    if (tid < 128) { sb1[tid] = bn1[tid]; sb2[tid] = bn2[tid]; }
    __syncthreads();

    const int lane = tid & 31;
    const int wid  = tid >> 5;
    const int wm = wid & 3, wn = wid >> 2;
    float acc[2][4][4];

    for (int t = blockIdx.x; t < NODE_TILES; t += 148) {
        const int n0 = t * 128;

#pragma unroll
        for (int i = 0; i < 4; ++i) {
            const int idx = tid + i * 512;
            const int el = idx >> 4, c = idx & 15;
            const int n = n0 + el;
            float4 v = make_float4(0.f, 0.f, 0.f, 0.f);
            if (n < N_NODES) v = *(const float4*)(g_h16 + (size_t)n * 128 + c * 8);
            *(float4*)(aB + el * 528 + c * 16) = v;
        }
#pragma unroll
        for (int i = 0; i < 8; ++i) {
            const int idx = tid + i * 512;
            const int el = idx >> 5, c = idx & 31;
            const int n = n0 + el;
            float4 v = make_float4(0.f, 0.f, 0.f, 0.f);
            if (n < N_NODES) v = ((const float4*)g_hagg)[(size_t)n * 32 + c];
            half2 h0 = __floats2half2_rn(v.x, v.y);
            half2 h1 = __floats2half2_rn(v.z, v.w);
            *(uint2*)(aB + el * 528 + 256 + c * 8) =
                make_uint2(*(uint32_t*)&h0, *(uint32_t*)&h1);
        }
        __syncthreads();

        zero_acc32(acc);
        gemm512(aU, 264, w1U, 16, acc);
        __syncthreads();
        {
#pragma unroll
            for (int mt = 0; mt < 2; ++mt)
#pragma unroll
                for (int nt = 0; nt < 4; ++nt) {
                    const int row = wm * 32 + mt * 16 + (lane >> 2);
                    const int col = wn * 32 + nt * 8 + (lane & 3) * 2;
                    const float b0 = sb1[col], b1v = sb1[col + 1];
                    *(half2*)(act + row * 136 + col) =
                        __floats2half2_rn(silu_f(acc[mt][nt][0] + b0), silu_f(acc[mt][nt][1] + b1v));
                    *(half2*)(act + (row + 8) * 136 + col) =
                        __floats2half2_rn(silu_f(acc[mt][nt][2] + b0), silu_f(acc[mt][nt][3] + b1v));
                }
        }
        __syncthreads();

        zero_acc32(acc);
        gemm512(actU, 136, w2U, 8, acc);

#pragma unroll
        for (int mt = 0; mt < 2; ++mt)
#pragma unroll
            for (int nt = 0; nt < 4; ++nt) {
                const int row = wm * 32 + mt * 16 + (lane >> 2);
                const int col = wn * 32 + nt * 8 + (lane & 3) * 2;
                const float b0 = sb2[col], b1v = sb2[col + 1];
                int n = n0 + row;
                if (n < N_NODES) {
                    float2 hv = *(const float2*)(hmat + (size_t)n * 128 + col);
                    *(float2*)(out + (size_t)n * 128 + col) =
                        make_float2(hv.x + acc[mt][nt][0] + b0, hv.y + acc[mt][nt][1] + b1v);
                }
                n = n0 + row + 8;
                if (n < N_NODES) {
                    float2 hv = *(const float2*)(hmat + (size_t)n * 128 + col);
                    *(float2*)(out + (size_t)n * 128 + col) =
                        make_float2(hv.x + acc[mt][nt][2] + b0, hv.y + acc[mt][nt][3] + b1v);
                }
            }

        if (tid < 128) {
            const int n = n0 + tid;
            if (n < N_NODES) {
                const size_t base = (size_t)N_NODES * 128;
                out[base + n * 3 + 0] = coords[n * 3 + 0] + g_xagg[n * 3 + 0];
                out[base + n * 3 + 1] = coords[n * 3 + 1] + g_xagg[n * 3 + 1];
                out[base + n * 3 + 2] = coords[n * 3 + 2] + g_xagg[n * 3 + 2];
            }
        }
        __syncthreads();
    }
}

// ---------------------------------------------------------------------------
extern "C" void kernel_launch(void* const* d_in, const int* in_sizes, int n_in,
                              void* d_out, int out_size)
{
    const float* h      = (const float*)d_in[0];
    const float* coords = (const float*)d_in[1];
    const float* a      = (const float*)d_in[2];
    const int*   src    = (const int*)d_in[3];
    const int*   dst    = (const int*)d_in[4];
    const float* We1 = (const float*)d_in[5];
    const float* be1 = (const float*)d_in[6];
    const float* We2 = (const float*)d_in[7];
    const float* be2 = (const float*)d_in[8];
    const float* Wa  = (const float*)d_in[9];
    const float* ba  = (const float*)d_in[10];
    const float* Wn1 = (const float*)d_in[11];
    const float* bn1 = (const float*)d_in[12];
    const float* Wn2 = (const float*)d_in[13];
    const float* bn2 = (const float*)d_in[14];
    const float* Wc1 = (const float*)d_in[15];
    const float* bc1 = (const float*)d_in[16];
    const float* Wc2 = (const float*)d_in[17];
    const float* bc2 = (const float*)d_in[18];
    const float* Wc3 = (const float*)d_in[19];
    float* out = (float*)d_out;

    __half *dW1e, *dW1c, *dWe2, *dWc2;
    cudaGetSymbolAddress((void**)&dW1e, g_W1e);
    cudaGetSymbolAddress((void**)&dW1c, g_W1c);
    cudaGetSymbolAddress((void**)&dWe2, g_We2);
    cudaGetSymbolAddress((void**)&dWc2, g_Wc2);

    cudaFuncSetAttribute(precompute_kernel, cudaFuncAttributeMaxDynamicSharedMemorySize, PC_SMEM);
    cudaFuncSetAttribute(edge_fat_kernel, cudaFuncAttributeMaxDynamicSharedMemorySize, EDGE_SMEM);
    cudaFuncSetAttribute(node_kernel, cudaFuncAttributeMaxDynamicSharedMemorySize, NODE_SMEM);

    prep_kernel<<<1024, 256>>>(h, a, We1, Wc1, We2, Wc2, Wn1, Wn2);
    precompute_kernel<<<148, 512, PC_SMEM>>>(be1, bc1);
    edge_fat_kernel<<<148, 512, EDGE_SMEM>>>(
        coords, src, dst, dW1e, dWe2, dW1c, dWc2,
        be2, Wa, ba, bc2, Wc3);
    node_kernel<<<148, 512, NODE_SMEM>>>(h, coords, bn1, bn2, out);
}

// round 16
// speedup vs baseline: 1.8093x; 1.0957x over previous
#include <cuda_runtime.h>
#include <cuda_fp16.h>
#include <cstdint>
#include <math.h>

#define N_NODES 50000
#define E_EDGES 800000
#define H 128
#define MF 276
#define NTILES64 (E_EDGES / 64)             // 12500 64-edge tiles
#define NSTREAMS 148                        // 74 CTAs/mode x 2 groups
#define NODE_TILES ((N_NODES + 127) / 128)  // 391

// ---------------------------------------------------------------------------
__device__ float  g_hagg[N_NODES * H];
__device__ float  g_xagg[N_NODES * 3];
__device__ __half g_h16[N_NODES * H];
__device__ __half g_a16[E_EDGES * 16];
__device__ __half g_W1e[288 * 136];
__device__ __half g_W1c[288 * 136];
__device__ __half g_We2[128 * 136];
__device__ __half g_Wc2[128 * 136];
__device__ __half g_Wn1[256 * 136];
__device__ __half g_Wn2[128 * 136];
__device__ __half g_P1e[N_NODES * H];   // h@We1_top + be1 (bias folded)
__device__ __half g_P2e[N_NODES * H];
__device__ __half g_P1c[N_NODES * H];   // h@Wc1_top + bc1
__device__ __half g_P2c[N_NODES * H];

__device__ __forceinline__ uint32_t smem_u32(const void* p) {
    uint32_t a;
    asm("{ .reg .u64 t; cvta.to.shared.u64 t, %1; cvt.u32.u64 %0, t; }"
        : "=r"(a) : "l"(p));
    return a;
}
__device__ __forceinline__ float tanh_f(float x) {
    float y;
    asm("tanh.approx.f32 %0, %1;" : "=f"(y) : "f"(x));
    return y;
}
__device__ __forceinline__ float silu_f(float v) {
    const float hv = 0.5f * v;
    return fmaf(hv, tanh_f(hv), hv);
}
__device__ __forceinline__ float sigmoid_f(float x) {
    return fmaf(0.5f, tanh_f(0.5f * x), 0.5f);
}
__device__ __forceinline__ void red_add_v4(float* p, float a, float b, float c, float d) {
    asm volatile("red.global.add.v4.f32 [%0], {%1,%2,%3,%4};"
        :: "l"(p), "f"(a), "f"(b), "f"(c), "f"(d) : "memory");
}
__device__ __forceinline__ uint4 hadd2x4(uint4 a, uint4 b) {
    uint4 r;
    half2* ra = (half2*)&a; half2* rb = (half2*)&b; half2* rr = (half2*)&r;
#pragma unroll
    for (int i = 0; i < 4; ++i) rr[i] = __hadd2(ra[i], rb[i]);
    return r;
}
#define GBAR(id) asm volatile("bar.sync %0, 256;" :: "r"(id) : "memory")

// ---------------------------------------------------------------------------
// Group GEMM (fp32 acc): 8 warps in 2(M)x4(N); C tile 64x128.
// ---------------------------------------------------------------------------
__device__ __forceinline__ void zero_acc(float (&acc)[2][4][4]) {
#pragma unroll
    for (int mt = 0; mt < 2; ++mt)
#pragma unroll
        for (int nt = 0; nt < 4; ++nt)
#pragma unroll
            for (int i = 0; i < 4; ++i) acc[mt][nt][i] = 0.f;
}

__device__ __forceinline__ void gemm_g(uint32_t aBase, int aStride,
                                       uint32_t bBase, int ksteps,
                                       float (&acc)[2][4][4])
{
    const int lane = threadIdx.x & 31;
    const int wid  = (threadIdx.x >> 5) & 7;
    const int wm   = wid & 1;
    const int wn   = wid >> 1;
    const int arow = wm * 32 + (lane & 15);
    const int acoff = (lane & 16) ? 8 : 0;
    const int brow = lane & 15;
    const int bcol = wn * 32 + ((lane & 16) ? 8 : 0);

    for (int ks = 0; ks < ksteps; ++ks) {
        const int k0 = ks * 16;
        uint32_t a[2][4];
#pragma unroll
        for (int mt = 0; mt < 2; ++mt) {
            uint32_t ad = aBase + (uint32_t)(((arow + mt * 16) * aStride + k0 + acoff) * 2);
            asm volatile("ldmatrix.sync.aligned.m8n8.x4.shared.b16 {%0,%1,%2,%3}, [%4];"
                : "=r"(a[mt][0]), "=r"(a[mt][1]), "=r"(a[mt][2]), "=r"(a[mt][3]) : "r"(ad));
        }
        uint32_t b[4][2];
#pragma unroll
        for (int nt2 = 0; nt2 < 2; ++nt2) {
            uint32_t bd = bBase + (uint32_t)(((k0 + brow) * 136 + bcol + nt2 * 16) * 2);
            asm volatile("ldmatrix.sync.aligned.m8n8.x4.trans.shared.b16 {%0,%1,%2,%3}, [%4];"
                : "=r"(b[2 * nt2][0]), "=r"(b[2 * nt2][1]),
                  "=r"(b[2 * nt2 + 1][0]), "=r"(b[2 * nt2 + 1][1]) : "r"(bd));
        }
#pragma unroll
        for (int mt = 0; mt < 2; ++mt)
#pragma unroll
            for (int nt = 0; nt < 4; ++nt)
                asm volatile("mma.sync.aligned.m16n8k16.row.col.f32.f16.f16.f32 "
                    "{%0,%1,%2,%3}, {%4,%5,%6,%7}, {%8,%9}, {%0,%1,%2,%3};"
                    : "+f"(acc[mt][nt][0]), "+f"(acc[mt][nt][1]),
                      "+f"(acc[mt][nt][2]), "+f"(acc[mt][nt][3])
                    : "r"(a[mt][0]), "r"(a[mt][1]), "r"(a[mt][2]), "r"(a[mt][3]),
                      "r"(b[nt][0]), "r"(b[nt][1]));
    }
}

// E1: act = silu(acc + Psum)   (bias folded into Psum)
__device__ __forceinline__ void epi_fuse_g(const float (&acc)[2][4][4],
                                           const __half* __restrict__ Psum,
                                           __half* act)
{
    const int lane = threadIdx.x & 31;
    const int wid  = (threadIdx.x >> 5) & 7;
    const int wm = wid & 1, wn = wid >> 1;
#pragma unroll
    for (int mt = 0; mt < 2; ++mt)
#pragma unroll
        for (int nt = 0; nt < 4; ++nt) {
            const int row = wm * 32 + mt * 16 + (lane >> 2);
            const int col = wn * 32 + nt * 8 + (lane & 3) * 2;
#pragma unroll
            for (int rr = 0; rr < 2; ++rr) {
                const int r = row + rr * 8;
                float2 ps = __half22float2(*(const half2*)(Psum + r * 136 + col));
                float v0 = acc[mt][nt][2 * rr + 0] + ps.x;
                float v1 = acc[mt][nt][2 * rr + 1] + ps.y;
                *(half2*)(act + r * 136 + col) =
                    __floats2half2_rn(silu_f(v0), silu_f(v1));
            }
        }
}

// ---------------------------------------------------------------------------
// 512-thread GEMM (16 warps 4x4), C tile 128x128
// ---------------------------------------------------------------------------
__device__ __forceinline__ void zero_acc32(float (&acc)[2][4][4]) { zero_acc(acc); }

__device__ __forceinline__ void gemm512(uint32_t aBase, int aStride,
                                        uint32_t bBase, int ksteps,
                                        float (&acc)[2][4][4])
{
    const int lane = threadIdx.x & 31;
    const int wid  = threadIdx.x >> 5;
    const int wm   = wid & 3;
    const int wn   = wid >> 2;
    const int arow = wm * 32 + (lane & 15);
    const int acoff = (lane & 16) ? 8 : 0;
    const int brow = lane & 15;
    const int bcol = wn * 32 + ((lane & 16) ? 8 : 0);

    for (int ks = 0; ks < ksteps; ++ks) {
        const int k0 = ks * 16;
        uint32_t a[2][4];
#pragma unroll
        for (int mt = 0; mt < 2; ++mt) {
            uint32_t ad = aBase + (uint32_t)(((arow + mt * 16) * aStride + k0 + acoff) * 2);
            asm volatile("ldmatrix.sync.aligned.m8n8.x4.shared.b16 {%0,%1,%2,%3}, [%4];"
                : "=r"(a[mt][0]), "=r"(a[mt][1]), "=r"(a[mt][2]), "=r"(a[mt][3]) : "r"(ad));
        }
        uint32_t b[4][2];
#pragma unroll
        for (int nt2 = 0; nt2 < 2; ++nt2) {
            uint32_t bd = bBase + (uint32_t)(((k0 + brow) * 136 + bcol + nt2 * 16) * 2);
            asm volatile("ldmatrix.sync.aligned.m8n8.x4.trans.shared.b16 {%0,%1,%2,%3}, [%4];"
                : "=r"(b[2 * nt2][0]), "=r"(b[2 * nt2][1]),
                  "=r"(b[2 * nt2 + 1][0]), "=r"(b[2 * nt2 + 1][1]) : "r"(bd));
        }
#pragma unroll
        for (int mt = 0; mt < 2; ++mt)
#pragma unroll
            for (int nt = 0; nt < 4; ++nt)
                asm volatile("mma.sync.aligned.m16n8k16.row.col.f32.f16.f16.f32 "
                    "{%0,%1,%2,%3}, {%4,%5,%6,%7}, {%8,%9}, {%0,%1,%2,%3};"
                    : "+f"(acc[mt][nt][0]), "+f"(acc[mt][nt][1]),
                      "+f"(acc[mt][nt][2]), "+f"(acc[mt][nt][3])
                    : "r"(a[mt][0]), "r"(a[mt][1]), "r"(a[mt][2]), "r"(a[mt][3]),
                      "r"(b[nt][0]), "r"(b[nt][1]));
    }
}

// ---------------------------------------------------------------------------
__global__ void prep_kernel(const float* __restrict__ hmat, const float* __restrict__ amat,
                            const float* __restrict__ We1, const float* __restrict__ Wc1,
                            const float* __restrict__ We2, const float* __restrict__ Wc2,
                            const float* __restrict__ Wn1, const float* __restrict__ Wn2)
{
    const int stride = gridDim.x * blockDim.x;
    const int tid0 = blockIdx.x * blockDim.x + threadIdx.x;
    const __half hz = __float2half_rn(0.f);
    for (int i = tid0; i < N_NODES * H / 2; i += stride) {
        float2 v = ((const float2*)hmat)[i];
        ((half2*)g_h16)[i] = __floats2half2_rn(v.x, v.y);
    }
    for (int i = tid0; i < E_EDGES * 8; i += stride) {
        float2 v = ((const float2*)amat)[i];
        ((half2*)g_a16)[i] = __floats2half2_rn(v.x, v.y);
    }
    for (int i = tid0; i < 288 * 136; i += stride) {
        int k = i / 136, n = i % 136;
        bool ok = (k < MF) && (n < 128);
        g_W1e[i] = ok ? __float2half_rn(We1[k * 128 + n]) : hz;
        g_W1c[i] = ok ? __float2half_rn(Wc1[k * 128 + n]) : hz;
    }
    for (int i = tid0; i < 256 * 136; i += stride) {
        int k = i / 136, n = i % 136;
        g_Wn1[i] = (n < 128) ? __float2half_rn(Wn1[k * 128 + n]) : hz;
    }
    for (int i = tid0; i < 128 * 136; i += stride) {
        int k = i / 136, n = i % 136;
        bool ok = (n < 128);
        g_We2[i] = ok ? __float2half_rn(We2[k * 128 + n]) : hz;
        g_Wc2[i] = ok ? __float2half_rn(Wc2[k * 128 + n]) : hz;
        g_Wn2[i] = ok ? __float2half_rn(Wn2[k * 128 + n]) : hz;
    }
    for (int i = tid0; i < N_NODES * H; i += stride) g_hagg[i] = 0.f;
    for (int i = tid0; i < N_NODES * 3; i += stride) g_xagg[i] = 0.f;
}

// ---------------------------------------------------------------------------
// precompute: P1e=h@We1_top+be1, P2e=h@We1_bot, P1c=h@Wc1_top+bc1, P2c=h@Wc1_bot
// ---------------------------------------------------------------------------
#define PC_A     0
#define PC_W     34816
#define PC_SMEM  174080

__global__ void __launch_bounds__(512, 1)
precompute_kernel(const float* __restrict__ be1, const float* __restrict__ bc1)
{
    extern __shared__ __align__(16) char sm[];
    __half* A  = (__half*)(sm + PC_A);
    const uint32_t aU = smem_u32(A);
    const uint32_t wU = smem_u32(sm + PC_W);
    const int tid = threadIdx.x;

    for (int i = tid; i < 4352; i += 512)
        ((float4*)(sm + PC_W))[i] = ((const float4*)g_W1e)[i];
    for (int i = tid; i < 4352; i += 512)
        ((float4*)(sm + PC_W + 69632))[i] = ((const float4*)g_W1c)[i];
    __syncthreads();

    const int lane = tid & 31;
    const int wid  = tid >> 5;
    const int wm = wid & 3, wn = wid >> 2;
    __half* gP[4] = { g_P1e, g_P2e, g_P1c, g_P2c };
    float acc[2][4][4];

    for (int t = blockIdx.x; t < NODE_TILES; t += 148) {
        const int n0 = t * 128;
#pragma unroll
        for (int i = 0; i < 4; ++i) {
            const int idx = tid + i * 512;
            const int el = idx >> 4, c = idx & 15;
            const int n = n0 + el;
            float4 v = make_float4(0.f, 0.f, 0.f, 0.f);
            if (n < N_NODES) v = *(const float4*)(g_h16 + (size_t)n * 128 + c * 8);
            *(float4*)((char*)A + el * 272 + c * 16) = v;
        }
        __syncthreads();

#pragma unroll
        for (int j = 0; j < 4; ++j) {
            zero_acc32(acc);
            gemm512(aU, 136, wU + j * 34816, 8, acc);
            __half* P = gP[j];
            const float* bias = (j == 0) ? be1 : ((j == 2) ? bc1 : nullptr);
#pragma unroll
            for (int mt = 0; mt < 2; ++mt)
#pragma unroll
                for (int nt = 0; nt < 4; ++nt) {
                    const int row = wm * 32 + mt * 16 + (lane >> 2);
                    const int col = wn * 32 + nt * 8 + (lane & 3) * 2;
                    const float b0 = bias ? bias[col] : 0.f;
                    const float b1 = bias ? bias[col + 1] : 0.f;
                    int n = n0 + row;
                    if (n < N_NODES)
                        *(half2*)(P + (size_t)n * 128 + col) =
                            __floats2half2_rn(acc[mt][nt][0] + b0, acc[mt][nt][1] + b1);
                    n = n0 + row + 8;
                    if (n < N_NODES)
                        *(half2*)(P + (size_t)n * 128 + col) =
                            __floats2half2_rn(acc[mt][nt][2] + b0, acc[mt][nt][3] + b1);
                }
        }
        __syncthreads();
    }
}

// ---------------------------------------------------------------------------
// Fat persistent edge kernel: factorized layer-1, fused Psum, 3 barriers/tile,
// register-direct scatter (mode0).
// ---------------------------------------------------------------------------
#define EOF_W1S   0           // 32 x 136 h = 8704
#define EOF_W2    8704        // 34816
#define EOF_B2    43520
#define EOF_HW    44032
#define EOF_GRP   44544
#define GRP_PS    0           // Psum: 64 x 136 h = 17408
#define GRP_FSM   17408       // 64 x 40 h = 5120
#define GRP_ACT   22528       // 17408
#define GRP_SD    39936       // 2 x 1024
#define GRP_SIDX  41984       // 2 x 512
#define GRP_SPART 43008       // 64 x 4 f = 1024
#define GRP_SIZE  44032
#define EDGE_SMEM (EOF_GRP + 2 * GRP_SIZE)   // 132608

__global__ void __launch_bounds__(512, 1)
edge_fat_kernel(const float* __restrict__ coords,
                const int* __restrict__ src, const int* __restrict__ dst,
                const __half* __restrict__ gW1e, const __half* __restrict__ gW2e,
                const __half* __restrict__ gW1c, const __half* __restrict__ gW2c,
                const float* __restrict__ be2,
                const float* __restrict__ Wa,  const float* __restrict__ ba,
                const float* __restrict__ bc2,
                const float* __restrict__ Wc3)
{
    extern __shared__ __align__(16) char sm[];
    float* sb2  = (float*)(sm + EOF_B2);
    float* shw  = (float*)(sm + EOF_HW);

    const int tid  = threadIdx.x;
    const int g    = tid >> 8;
    const int gtid = tid & 255;
    const int bar  = g + 1;
    const int mode = blockIdx.x & 1;
    const int cb   = blockIdx.x >> 1;

    char* grp = sm + EOF_GRP + g * GRP_SIZE;
    __half* Ps  = (__half*)(grp + GRP_PS);
    char*   fsm = grp + GRP_FSM;
    __half* act = (__half*)(grp + GRP_ACT);
    int*    sidx = (int*)(grp + GRP_SIDX);
    float*  spart = (float*)(grp + GRP_SPART);

    const uint32_t fsmU = smem_u32(fsm), actU = smem_u32(act);
    const uint32_t w1sU = smem_u32(sm + EOF_W1S), w2U = smem_u32(sm + EOF_W2);

    const __half* gW1 = mode ? gW1c : gW1e;
    const __half* gW2 = mode ? gW2c : gW2e;
    const __half* gP1 = mode ? g_P1c : g_P1e;
    const __half* gP2 = mode ? g_P2c : g_P2e;
    const float*  b2  = mode ? bc2 : be2;
    const float*  hw  = mode ? Wc3 : Wa;
    const float   hb0 = mode ? 0.f : ba[0];

    for (int i = tid; i < 544; i += 512)
        ((float4*)(sm + EOF_W1S))[i] = ((const float4*)(gW1 + 256 * 136))[i];
    for (int i = tid; i < 2176; i += 512)
        ((float4*)(sm + EOF_W2))[i] = ((const float4*)gW2)[i];
    if (tid < 128) { sb2[tid] = b2[tid]; shw[tid] = hw[tid]; }
    if (gtid < 64) {  // zero-pad fsm cols 20..31
        *(uint2*)(fsm + gtid * 80 + 40) = make_uint2(0, 0);
        *(uint2*)(fsm + gtid * 80 + 48) = make_uint2(0, 0);
        *(uint2*)(fsm + gtid * 80 + 56) = make_uint2(0, 0);
    }
    __syncthreads();

    const int t0 = cb * 2 + g;
    float pdx = 0.f, pdy = 0.f, pdz = 0.f, pr = 0.f;

    // ---------------- prologue: gather tile t0 ----------------
    if (gtid < 64) {
        const int e = t0 * 64 + gtid;
        const int s_ = src[e], d_ = dst[e];
        sidx[gtid] = s_; sidx[64 + gtid] = d_;
        pdx = coords[s_ * 3 + 0] - coords[d_ * 3 + 0];
        pdy = coords[s_ * 3 + 1] - coords[d_ * 3 + 1];
        pdz = coords[s_ * 3 + 2] - coords[d_ * 3 + 2];
        pr  = sqrtf(pdx * pdx + pdy * pdy + pdz * pdz);
        if (mode == 1) {
            float* sd = (float*)(grp + GRP_SD);
            sd[4 * gtid + 0] = pdx; sd[4 * gtid + 1] = pdy;
            sd[4 * gtid + 2] = pdz; sd[4 * gtid + 3] = pr;
        }
    }
    GBAR(bar);
    {
#pragma unroll
        for (int i = 0; i < 4; ++i) {
            const int idx = gtid + i * 256;
            const int el = idx >> 4, c = idx & 15;
            uint4 p1 = *(const uint4*)(gP1 + (size_t)sidx[el] * 128 + c * 8);
            uint4 p2 = *(const uint4*)(gP2 + (size_t)sidx[64 + el] * 128 + c * 8);
            *(uint4*)((char*)Ps + el * 272 + c * 16) = hadd2x4(p1, p2);
        }
        {
            const int row = gtid >> 2, part = gtid & 3;
            uint2 v = *(const uint2*)(g_a16 + (size_t)(t0 * 64 + row) * 16 + part * 4);
            *(uint2*)(fsm + row * 80 + 8 + part * 8) = v;
        }
        if (gtid < 64) {
            half2 d0 = __floats2half2_rn(pr, fabsf(pdx));
            half2 d1 = __floats2half2_rn(fabsf(pdy), fabsf(pdz));
            *(uint2*)(fsm + gtid * 80) = make_uint2(*(uint32_t*)&d0, *(uint32_t*)&d1);
        }
    }
    GBAR(bar);

    float acc[2][4][4];
    int buf = 0;
    const int lane = tid & 31;
    const int wvid = (tid >> 5) & 7;
    const int wm = wvid & 1, wn = wvid >> 1;

    // ---------------- persistent tile loop (3 barriers) ----------------
    for (int t = t0; t < NTILES64; t += NSTREAMS) {
        const int tn = t + NSTREAMS;
        const int nbuf = buf ^ 1;
        const bool pf = (tn < NTILES64);
        uint4 rw[4];
        uint2 aR = make_uint2(0, 0);

        if (pf && gtid < 64) {
            const int e = tn * 64 + gtid;
            const int s_ = src[e], d_ = dst[e];
            sidx[nbuf * 128 + gtid] = s_;
            sidx[nbuf * 128 + 64 + gtid] = d_;
            pdx = coords[s_ * 3 + 0] - coords[d_ * 3 + 0];
            pdy = coords[s_ * 3 + 1] - coords[d_ * 3 + 1];
            pdz = coords[s_ * 3 + 2] - coords[d_ * 3 + 2];
            pr  = sqrtf(pdx * pdx + pdy * pdy + pdz * pdz);
            if (mode == 1) {
                float* sd = (float*)(grp + GRP_SD + nbuf * 1024);
                sd[4 * gtid + 0] = pdx; sd[4 * gtid + 1] = pdy;
                sd[4 * gtid + 2] = pdz; sd[4 * gtid + 3] = pr;
            }
        }

        // gather for tn: Psum in registers (indices straight from global)
        if (pf) {
#pragma unroll
            for (int i = 0; i < 4; ++i) {
                const int idx = gtid + i * 256;
                const int el = idx >> 4, c = idx & 15;
                const int e = tn * 64 + el;
                uint4 p1 = *(const uint4*)(gP1 + (size_t)__ldg(src + e) * 128 + c * 8);
                uint4 p2 = *(const uint4*)(gP2 + (size_t)__ldg(dst + e) * 128 + c * 8);
                rw[i] = hadd2x4(p1, p2);
            }
            aR = *(const uint2*)(g_a16 + (size_t)(tn * 64 + (gtid >> 2)) * 16 + (gtid & 3) * 4);
        }

        // G1small: [D|a] @ W1mid, K=32
        zero_acc(acc);
        gemm_g(fsmU, 40, w1sU, 2, acc);

        // E1: act = silu(acc + Psum)
        epi_fuse_g(acc, Ps, act);
        GBAR(bar);   // (1) Psum/fsm reads done; act visible

        // commit tn data, then G2
        if (pf) {
#pragma unroll
            for (int i = 0; i < 4; ++i) {
                const int idx = gtid + i * 256;
                const int el = idx >> 4, c = idx & 15;
                *(uint4*)((char*)Ps + el * 272 + c * 16) = rw[i];
            }
            *(uint2*)(fsm + (gtid >> 2) * 80 + 8 + (gtid & 3) * 8) = aR;
            if (gtid < 64) {
                half2 d0 = __floats2half2_rn(pr, fabsf(pdx));
                half2 d1 = __floats2half2_rn(fabsf(pdy), fabsf(pdz));
                *(uint2*)(fsm + gtid * 80) = make_uint2(*(uint32_t*)&d0, *(uint32_t*)&d1);
            }
        }
        zero_acc(acc);
        gemm_g(actU, 136, w2U, 8, acc);

        // E2a: silu in-place (acc <- silu vals) + partial head dot
        {
            float part[4] = {0.f, 0.f, 0.f, 0.f};
#pragma unroll
            for (int mt = 0; mt < 2; ++mt)
#pragma unroll
                for (int nt = 0; nt < 4; ++nt) {
                    const int col = wn * 32 + nt * 8 + (lane & 3) * 2;
                    const float b0 = sb2[col], b1v = sb2[col + 1];
                    const float w0 = shw[col], w1 = shw[col + 1];
                    const float v0 = silu_f(acc[mt][nt][0] + b0);
                    const float v1 = silu_f(acc[mt][nt][1] + b1v);
                    const float v2 = silu_f(acc[mt][nt][2] + b0);
                    const float v3 = silu_f(acc[mt][nt][3] + b1v);
                    acc[mt][nt][0] = v0; acc[mt][nt][1] = v1;
                    acc[mt][nt][2] = v2; acc[mt][nt][3] = v3;
                    part[mt * 2 + 0] = fmaf(v0, w0, fmaf(v1, w1, part[mt * 2 + 0]));
                    part[mt * 2 + 1] = fmaf(v2, w0, fmaf(v3, w1, part[mt * 2 + 1]));
                }
#pragma unroll
            for (int k = 0; k < 4; ++k) {
                part[k] += __shfl_xor_sync(0xFFFFFFFFu, part[k], 1);
                part[k] += __shfl_xor_sync(0xFFFFFFFFu, part[k], 2);
            }
            if ((lane & 3) == 0) {
                const int rsel = lane >> 2;
                spart[(wm * 32 +  0 + rsel) * 4 + wn] = part[0];
                spart[(wm * 32 +  8 + rsel) * 4 + wn] = part[1];
                spart[(wm * 32 + 16 + rsel) * 4 + wn] = part[2];
                spart[(wm * 32 + 24 + rsel) * 4 + wn] = part[3];
            }
        }
        GBAR(bar);   // (2) spart visible

        if (mode == 0) {
            // E2b: per-quad att computation (variant v = lane&3 -> row rv)
            const int v = lane & 3;
            const int rv = wm * 32 + (v >> 1) * 16 + (v & 1) * 8 + (lane >> 2);
            const float dotv = spart[rv * 4 + 0] + spart[rv * 4 + 1]
                             + spart[rv * 4 + 2] + spart[rv * 4 + 3];
            const float attv = sigmoid_f(dotv + hb0);
            float attArr[4];
#pragma unroll
            for (int k = 0; k < 4; ++k)
                attArr[k] = __shfl_sync(0xFFFFFFFFu, attv, (lane & ~3) | k);
            // scatter from registers: pair lanes, even lane issues red.v4
#pragma unroll
            for (int mt = 0; mt < 2; ++mt)
#pragma unroll
                for (int rr = 0; rr < 2; ++rr) {
                    const int row = wm * 32 + mt * 16 + rr * 8 + (lane >> 2);
                    const float att = attArr[mt * 2 + rr];
                    const int d_ = sidx[buf * 128 + 64 + row];
#pragma unroll
                    for (int nt = 0; nt < 4; ++nt) {
                        float s0 = att * acc[mt][nt][2 * rr + 0];
                        float s1 = att * acc[mt][nt][2 * rr + 1];
                        float n0 = __shfl_xor_sync(0xFFFFFFFFu, s0, 1);
                        float n1 = __shfl_xor_sync(0xFFFFFFFFu, s1, 1);
                        if ((lane & 1) == 0) {
                            const int col = wn * 32 + nt * 8 + (lane & 3) * 2;
                            red_add_v4(g_hagg + (size_t)d_ * 128 + col, s0, s1, n0, n1);
                        }
                    }
                }
        } else {
            if (gtid < 64) {
                const float dot = spart[gtid * 4 + 0] + spart[gtid * 4 + 1]
                                + spart[gtid * 4 + 2] + spart[gtid * 4 + 3];
                const float* sd = (const float*)(grp + GRP_SD + buf * 1024);
                const float dx = sd[4 * gtid + 0], dy = sd[4 * gtid + 1];
                const float dz = sd[4 * gtid + 2], r  = sd[4 * gtid + 3];
                const float gg = dot / (r + 1.f);
                const int d_ = sidx[buf * 128 + 64 + gtid];
                atomicAdd(&g_xagg[d_ * 3 + 0], gg * dx);
                atomicAdd(&g_xagg[d_ * 3 + 1], gg * dy);
                atomicAdd(&g_xagg[d_ * 3 + 2], gg * dz);
            }
        }
        GBAR(bar);   // (3) end of tile
        buf = nbuf;
    }
}

// ---------------------------------------------------------------------------
// Persistent node kernel (f32 tanh silu)
// ---------------------------------------------------------------------------
#define NOF_W1   0
#define NOF_W2   69632
#define NOF_A    104448
#define NOF_ACT  172032
#define NOF_B    206848
#define NODE_SMEM 207872

__global__ void __launch_bounds__(512, 1)
node_kernel(const float* __restrict__ hmat, const float* __restrict__ coords,
            const float* __restrict__ bn1, const float* __restrict__ bn2,
            float* __restrict__ out)
{
    extern __shared__ __align__(16) char sm[];
    __half* sW1 = (__half*)(sm + NOF_W1);
    __half* sW2 = (__half*)(sm + NOF_W2);
    char*   aB  = sm + NOF_A;
    __half* act = (__half*)(sm + NOF_ACT);
    float* sb1  = (float*)(sm + NOF_B);
    float* sb2  = sb1 + 128;

    const uint32_t aU = smem_u32(aB), w1U = smem_u32(sW1);
    const uint32_t w2U = smem_u32(sW2), actU = smem_u32(act);
    const int tid = threadIdx.x;

    for (int i = tid; i < 4352; i += 512) ((float4*)sW1)[i] = ((const float4*)g_Wn1)[i];
    for (int i = tid; i < 2176; i += 512) ((float4*)sW2)[i] = ((const float4*)g_Wn2)[i];
    if (tid < 128) { sb1[tid] = bn1[tid]; sb2[tid] = bn2[tid]; }
    __syncthreads();

    const int lane = tid & 31;
    const int wid  = tid >> 5;
    const int wm = wid & 3, wn = wid >> 2;
    float acc[2][4][4];

    for (int t = blockIdx.x; t < NODE_TILES; t += 148) {
        const int n0 = t * 128;

#pragma unroll
        for (int i = 0; i < 4; ++i) {
            const int idx = tid + i * 512;
            const int el = idx >> 4, c = idx & 15;
            const int n = n0 + el;
            float4 v = make_float4(0.f, 0.f, 0.f, 0.f);
            if (n < N_NODES) v = *(const float4*)(g_h16 + (size_t)n * 128 + c * 8);
            *(float4*)(aB + el * 528 + c * 16) = v;
        }
#pragma unroll
        for (int i = 0; i < 8; ++i) {
            const int idx = tid + i * 512;
            const int el = idx >> 5, c = idx & 31;
            const int n = n0 + el;
            float4 v = make_float4(0.f, 0.f, 0.f, 0.f);
            if (n < N_NODES) v = ((const float4*)g_hagg)[(size_t)n * 32 + c];
            half2 h0 = __floats2half2_rn(v.x, v.y);
            half2 h1 = __floats2half2_rn(v.z, v.w);
            *(uint2*)(aB + el * 528 + 256 + c * 8) =
                make_uint2(*(uint32_t*)&h0, *(uint32_t*)&h1);
        }
        __syncthreads();

        zero_acc32(acc);
        gemm512(aU, 264, w1U, 16, acc);
        __syncthreads();
        {
#pragma unroll
            for (int mt = 0; mt < 2; ++mt)
#pragma unroll
                for (int nt = 0; nt < 4; ++nt) {
                    const int row = wm * 32 + mt * 16 + (lane >> 2);
                    const int col = wn * 32 + nt * 8 + (lane & 3) * 2;
                    const float b0 = sb1[col], b1v = sb1[col + 1];
                    *(half2*)(act + row * 136 + col) =
                        __floats2half2_rn(silu_f(acc[mt][nt][0] + b0), silu_f(acc[mt][nt][1] + b1v));
                    *(half2*)(act + (row + 8) * 136 + col) =
                        __floats2half2_rn(silu_f(acc[mt][nt][2] + b0), silu_f(acc[mt][nt][3] + b1v));
                }
        }
        __syncthreads();

        zero_acc32(acc);
        gemm512(actU, 136, w2U, 8, acc);

#pragma unroll
        for (int mt = 0; mt < 2; ++mt)
#pragma unroll
            for (int nt = 0; nt < 4; ++nt) {
                const int row = wm * 32 + mt * 16 + (lane >> 2);
                const int col = wn * 32 + nt * 8 + (lane & 3) * 2;
                const float b0 = sb2[col], b1v = sb2[col + 1];
                int n = n0 + row;
                if (n < N_NODES) {
                    float2 hv = *(const float2*)(hmat + (size_t)n * 128 + col);
                    *(float2*)(out + (size_t)n * 128 + col) =
                        make_float2(hv.x + acc[mt][nt][0] + b0, hv.y + acc[mt][nt][1] + b1v);
                }
                n = n0 + row + 8;
                if (n < N_NODES) {
                    float2 hv = *(const float2*)(hmat + (size_t)n * 128 + col);
                    *(float2*)(out + (size_t)n * 128 + col) =
                        make_float2(hv.x + acc[mt][nt][2] + b0, hv.y + acc[mt][nt][3] + b1v);
                }
            }

        if (tid < 128) {
            const int n = n0 + tid;
            if (n < N_NODES) {
                const size_t base = (size_t)N_NODES * 128;
                out[base + n * 3 + 0] = coords[n * 3 + 0] + g_xagg[n * 3 + 0];
                out[base + n * 3 + 1] = coords[n * 3 + 1] + g_xagg[n * 3 + 1];
                out[base + n * 3 + 2] = coords[n * 3 + 2] + g_xagg[n * 3 + 2];
            }
        }
        __syncthreads();
    }
}

// ---------------------------------------------------------------------------
extern "C" void kernel_launch(void* const* d_in, const int* in_sizes, int n_in,
                              void* d_out, int out_size)
{
    const float* h      = (const float*)d_in[0];
    const float* coords = (const float*)d_in[1];
    const float* a      = (const float*)d_in[2];
    const int*   src    = (const int*)d_in[3];
    const int*   dst    = (const int*)d_in[4];
    const float* We1 = (const float*)d_in[5];
    const float* be1 = (const float*)d_in[6];
    const float* We2 = (const float*)d_in[7];
    const float* be2 = (const float*)d_in[8];
    const float* Wa  = (const float*)d_in[9];
    const float* ba  = (const float*)d_in[10];
    const float* Wn1 = (const float*)d_in[11];
    const float* bn1 = (const float*)d_in[12];
    const float* Wn2 = (const float*)d_in[13];
    const float* bn2 = (const float*)d_in[14];
    const float* Wc1 = (const float*)d_in[15];
    const float* bc1 = (const float*)d_in[16];
    const float* Wc2 = (const float*)d_in[17];
    const float* bc2 = (const float*)d_in[18];
    const float* Wc3 = (const float*)d_in[19];
    float* out = (float*)d_out;

    __half *dW1e, *dW1c, *dWe2, *dWc2;
    cudaGetSymbolAddress((void**)&dW1e, g_W1e);
    cudaGetSymbolAddress((void**)&dW1c, g_W1c);
    cudaGetSymbolAddress((void**)&dWe2, g_We2);
    cudaGetSymbolAddress((void**)&dWc2, g_Wc2);

    cudaFuncSetAttribute(precompute_kernel, cudaFuncAttributeMaxDynamicSharedMemorySize, PC_SMEM);
    cudaFuncSetAttribute(edge_fat_kernel, cudaFuncAttributeMaxDynamicSharedMemorySize, EDGE_SMEM);
    cudaFuncSetAttribute(node_kernel, cudaFuncAttributeMaxDynamicSharedMemorySize, NODE_SMEM);

    prep_kernel<<<1024, 256>>>(h, a, We1, Wc1, We2, Wc2, Wn1, Wn2);
    precompute_kernel<<<148, 512, PC_SMEM>>>(be1, bc1);
    edge_fat_kernel<<<148, 512, EDGE_SMEM>>>(
        coords, src, dst, dW1e, dWe2, dW1c, dWc2,
        be2, Wa, ba, bc2, Wc3);
    node_kernel<<<148, 512, NODE_SMEM>>>(h, coords, bn1, bn2, out);
}

// round 17
// speedup vs baseline: 1.9677x; 1.0875x over previous
#include <cuda_runtime.h>
#include <cuda_fp16.h>
#include <cstdint>
#include <math.h>

#define N_NODES 50000
#define E_EDGES 800000
#define H 128
#define MF 276
#define NTILES32 (E_EDGES / 32)             // 25000 32-edge tiles
#define NSTREAMS 296                        // 74 CTAs/mode x 4 groups
#define NODE_TILES ((N_NODES + 127) / 128)  // 391

// ---------------------------------------------------------------------------
__device__ float  g_hagg[N_NODES * H];
__device__ float  g_xagg[N_NODES * 3];
__device__ __half g_h16[N_NODES * H];
__device__ __half g_a16[E_EDGES * 16];
__device__ __half g_W1e[288 * 136];
__device__ __half g_W1c[288 * 136];
__device__ __half g_We2[128 * 136];
__device__ __half g_Wc2[128 * 136];
__device__ __half g_Wn1[256 * 136];
__device__ __half g_Wn2[128 * 136];
__device__ __half g_P1e[N_NODES * H];   // h@We1_top + be1 (bias folded)
__device__ __half g_P2e[N_NODES * H];
__device__ __half g_P1c[N_NODES * H];   // h@Wc1_top + bc1
__device__ __half g_P2c[N_NODES * H];

__device__ __forceinline__ uint32_t smem_u32(const void* p) {
    uint32_t a;
    asm("{ .reg .u64 t; cvta.to.shared.u64 t, %1; cvt.u32.u64 %0, t; }"
        : "=r"(a) : "l"(p));
    return a;
}
__device__ __forceinline__ float tanh_f(float x) {
    float y;
    asm("tanh.approx.f32 %0, %1;" : "=f"(y) : "f"(x));
    return y;
}
__device__ __forceinline__ float silu_f(float v) {
    const float hv = 0.5f * v;
    return fmaf(hv, tanh_f(hv), hv);
}
__device__ __forceinline__ float sigmoid_f(float x) {
    return fmaf(0.5f, tanh_f(0.5f * x), 0.5f);
}
__device__ __forceinline__ void red_add_v4(float* p, float a, float b, float c, float d) {
    asm volatile("red.global.add.v4.f32 [%0], {%1,%2,%3,%4};"
        :: "l"(p), "f"(a), "f"(b), "f"(c), "f"(d) : "memory");
}
__device__ __forceinline__ uint4 hadd2x4(uint4 a, uint4 b) {
    uint4 r;
    half2* ra = (half2*)&a; half2* rb = (half2*)&b; half2* rr = (half2*)&r;
#pragma unroll
    for (int i = 0; i < 4; ++i) rr[i] = __hadd2(ra[i], rb[i]);
    return r;
}
#define GBAR(id) asm volatile("bar.sync %0, 128;" :: "r"(id) : "memory")

// ---------------------------------------------------------------------------
// Group GEMM (fp32 acc): 4 warps in 1(M)x4(N); C tile 32x128.
// Each warp: 32 rows x 32 cols = 2 mtiles x 4 ntiles m16n8, acc[2][4][4].
// ---------------------------------------------------------------------------
__device__ __forceinline__ void zero_acc(float (&acc)[2][4][4]) {
#pragma unroll
    for (int mt = 0; mt < 2; ++mt)
#pragma unroll
        for (int nt = 0; nt < 4; ++nt)
#pragma unroll
            for (int i = 0; i < 4; ++i) acc[mt][nt][i] = 0.f;
}

__device__ __forceinline__ void gemm_g(uint32_t aBase, int aStride,
                                       uint32_t bBase, int ksteps,
                                       float (&acc)[2][4][4])
{
    const int lane = threadIdx.x & 31;
    const int wn   = (threadIdx.x >> 5) & 3;
    const int arow = lane & 15;
    const int acoff = (lane & 16) ? 8 : 0;
    const int brow = lane & 15;
    const int bcol = wn * 32 + ((lane & 16) ? 8 : 0);

    for (int ks = 0; ks < ksteps; ++ks) {
        const int k0 = ks * 16;
        uint32_t a[2][4];
#pragma unroll
        for (int mt = 0; mt < 2; ++mt) {
            uint32_t ad = aBase + (uint32_t)(((arow + mt * 16) * aStride + k0 + acoff) * 2);
            asm volatile("ldmatrix.sync.aligned.m8n8.x4.shared.b16 {%0,%1,%2,%3}, [%4];"
                : "=r"(a[mt][0]), "=r"(a[mt][1]), "=r"(a[mt][2]), "=r"(a[mt][3]) : "r"(ad));
        }
        uint32_t b[4][2];
#pragma unroll
        for (int nt2 = 0; nt2 < 2; ++nt2) {
            uint32_t bd = bBase + (uint32_t)(((k0 + brow) * 136 + bcol + nt2 * 16) * 2);
            asm volatile("ldmatrix.sync.aligned.m8n8.x4.trans.shared.b16 {%0,%1,%2,%3}, [%4];"
                : "=r"(b[2 * nt2][0]), "=r"(b[2 * nt2][1]),
                  "=r"(b[2 * nt2 + 1][0]), "=r"(b[2 * nt2 + 1][1]) : "r"(bd));
        }
#pragma unroll
        for (int mt = 0; mt < 2; ++mt)
#pragma unroll
            for (int nt = 0; nt < 4; ++nt)
                asm volatile("mma.sync.aligned.m16n8k16.row.col.f32.f16.f16.f32 "
                    "{%0,%1,%2,%3}, {%4,%5,%6,%7}, {%8,%9}, {%0,%1,%2,%3};"
                    : "+f"(acc[mt][nt][0]), "+f"(acc[mt][nt][1]),
                      "+f"(acc[mt][nt][2]), "+f"(acc[mt][nt][3])
                    : "r"(a[mt][0]), "r"(a[mt][1]), "r"(a[mt][2]), "r"(a[mt][3]),
                      "r"(b[nt][0]), "r"(b[nt][1]));
    }
}

// E1: act = silu(acc + Psum)   (bias folded into Psum)
__device__ __forceinline__ void epi_fuse_g(const float (&acc)[2][4][4],
                                           const __half* __restrict__ Psum,
                                           __half* act)
{
    const int lane = threadIdx.x & 31;
    const int wn   = (threadIdx.x >> 5) & 3;
#pragma unroll
    for (int mt = 0; mt < 2; ++mt)
#pragma unroll
        for (int nt = 0; nt < 4; ++nt) {
            const int row = mt * 16 + (lane >> 2);
            const int col = wn * 32 + nt * 8 + (lane & 3) * 2;
#pragma unroll
            for (int rr = 0; rr < 2; ++rr) {
                const int r = row + rr * 8;
                float2 ps = __half22float2(*(const half2*)(Psum + r * 136 + col));
                float v0 = acc[mt][nt][2 * rr + 0] + ps.x;
                float v1 = acc[mt][nt][2 * rr + 1] + ps.y;
                *(half2*)(act + r * 136 + col) =
                    __floats2half2_rn(silu_f(v0), silu_f(v1));
            }
        }
}

// ---------------------------------------------------------------------------
// 512-thread GEMM (16 warps 4x4), C tile 128x128 (node + precompute)
// ---------------------------------------------------------------------------
__device__ __forceinline__ void zero_acc32(float (&acc)[2][4][4]) { zero_acc(acc); }

__device__ __forceinline__ void gemm512(uint32_t aBase, int aStride,
                                        uint32_t bBase, int ksteps,
                                        float (&acc)[2][4][4])
{
    const int lane = threadIdx.x & 31;
    const int wid  = threadIdx.x >> 5;
    const int wm   = wid & 3;
    const int wn   = wid >> 2;
    const int arow = wm * 32 + (lane & 15);
    const int acoff = (lane & 16) ? 8 : 0;
    const int brow = lane & 15;
    const int bcol = wn * 32 + ((lane & 16) ? 8 : 0);

    for (int ks = 0; ks < ksteps; ++ks) {
        const int k0 = ks * 16;
        uint32_t a[2][4];
#pragma unroll
        for (int mt = 0; mt < 2; ++mt) {
            uint32_t ad = aBase + (uint32_t)(((arow + mt * 16) * aStride + k0 + acoff) * 2);
            asm volatile("ldmatrix.sync.aligned.m8n8.x4.shared.b16 {%0,%1,%2,%3}, [%4];"
                : "=r"(a[mt][0]), "=r"(a[mt][1]), "=r"(a[mt][2]), "=r"(a[mt][3]) : "r"(ad));
        }
        uint32_t b[4][2];
#pragma unroll
        for (int nt2 = 0; nt2 < 2; ++nt2) {
            uint32_t bd = bBase + (uint32_t)(((k0 + brow) * 136 + bcol + nt2 * 16) * 2);
            asm volatile("ldmatrix.sync.aligned.m8n8.x4.trans.shared.b16 {%0,%1,%2,%3}, [%4];"
                : "=r"(b[2 * nt2][0]), "=r"(b[2 * nt2][1]),
                  "=r"(b[2 * nt2 + 1][0]), "=r"(b[2 * nt2 + 1][1]) : "r"(bd));
        }
#pragma unroll
        for (int mt = 0; mt < 2; ++mt)
#pragma unroll
            for (int nt = 0; nt < 4; ++nt)
                asm volatile("mma.sync.aligned.m16n8k16.row.col.f32.f16.f16.f32 "
                    "{%0,%1,%2,%3}, {%4,%5,%6,%7}, {%8,%9}, {%0,%1,%2,%3};"
                    : "+f"(acc[mt][nt][0]), "+f"(acc[mt][nt][1]),
                      "+f"(acc[mt][nt][2]), "+f"(acc[mt][nt][3])
                    : "r"(a[mt][0]), "r"(a[mt][1]), "r"(a[mt][2]), "r"(a[mt][3]),
                      "r"(b[nt][0]), "r"(b[nt][1]));
    }
}

// ---------------------------------------------------------------------------
__global__ void prep_kernel(const float* __restrict__ hmat, const float* __restrict__ amat,
                            const float* __restrict__ We1, const float* __restrict__ Wc1,
                            const float* __restrict__ We2, const float* __restrict__ Wc2,
                            const float* __restrict__ Wn1, const float* __restrict__ Wn2)
{
    const int stride = gridDim.x * blockDim.x;
    const int tid0 = blockIdx.x * blockDim.x + threadIdx.x;
    const __half hz = __float2half_rn(0.f);
    for (int i = tid0; i < N_NODES * H / 2; i += stride) {
        float2 v = ((const float2*)hmat)[i];
        ((half2*)g_h16)[i] = __floats2half2_rn(v.x, v.y);
    }
    for (int i = tid0; i < E_EDGES * 8; i += stride) {
        float2 v = ((const float2*)amat)[i];
        ((half2*)g_a16)[i] = __floats2half2_rn(v.x, v.y);
    }
    for (int i = tid0; i < 288 * 136; i += stride) {
        int k = i / 136, n = i % 136;
        bool ok = (k < MF) && (n < 128);
        g_W1e[i] = ok ? __float2half_rn(We1[k * 128 + n]) : hz;
        g_W1c[i] = ok ? __float2half_rn(Wc1[k * 128 + n]) : hz;
    }
    for (int i = tid0; i < 256 * 136; i += stride) {
        int k = i / 136, n = i % 136;
        g_Wn1[i] = (n < 128) ? __float2half_rn(Wn1[k * 128 + n]) : hz;
    }
    for (int i = tid0; i < 128 * 136; i += stride) {
        int k = i / 136, n = i % 136;
        bool ok = (n < 128);
        g_We2[i] = ok ? __float2half_rn(We2[k * 128 + n]) : hz;
        g_Wc2[i] = ok ? __float2half_rn(Wc2[k * 128 + n]) : hz;
        g_Wn2[i] = ok ? __float2half_rn(Wn2[k * 128 + n]) : hz;
    }
    for (int i = tid0; i < N_NODES * H; i += stride) g_hagg[i] = 0.f;
    for (int i = tid0; i < N_NODES * 3; i += stride) g_xagg[i] = 0.f;
}

// ---------------------------------------------------------------------------
// precompute: P1e=h@We1_top+be1, P2e=h@We1_bot, P1c=h@Wc1_top+bc1, P2c=h@Wc1_bot
// ---------------------------------------------------------------------------
#define PC_A     0
#define PC_W     34816
#define PC_SMEM  174080

__global__ void __launch_bounds__(512, 1)
precompute_kernel(const float* __restrict__ be1, const float* __restrict__ bc1)
{
    extern __shared__ __align__(16) char sm[];
    __half* A  = (__half*)(sm + PC_A);
    const uint32_t aU = smem_u32(A);
    const uint32_t wU = smem_u32(sm + PC_W);
    const int tid = threadIdx.x;

    for (int i = tid; i < 4352; i += 512)
        ((float4*)(sm + PC_W))[i] = ((const float4*)g_W1e)[i];
    for (int i = tid; i < 4352; i += 512)
        ((float4*)(sm + PC_W + 69632))[i] = ((const float4*)g_W1c)[i];
    __syncthreads();

    const int lane = tid & 31;
    const int wid  = tid >> 5;
    const int wm = wid & 3, wn = wid >> 2;
    __half* gP[4] = { g_P1e, g_P2e, g_P1c, g_P2c };
    float acc[2][4][4];

    for (int t = blockIdx.x; t < NODE_TILES; t += 148) {
        const int n0 = t * 128;
#pragma unroll
        for (int i = 0; i < 4; ++i) {
            const int idx = tid + i * 512;
            const int el = idx >> 4, c = idx & 15;
            const int n = n0 + el;
            float4 v = make_float4(0.f, 0.f, 0.f, 0.f);
            if (n < N_NODES) v = *(const float4*)(g_h16 + (size_t)n * 128 + c * 8);
            *(float4*)((char*)A + el * 272 + c * 16) = v;
        }
        __syncthreads();

#pragma unroll
        for (int j = 0; j < 4; ++j) {
            zero_acc32(acc);
            gemm512(aU, 136, wU + j * 34816, 8, acc);
            __half* P = gP[j];
            const float* bias = (j == 0) ? be1 : ((j == 2) ? bc1 : nullptr);
#pragma unroll
            for (int mt = 0; mt < 2; ++mt)
#pragma unroll
                for (int nt = 0; nt < 4; ++nt) {
                    const int row = wm * 32 + mt * 16 + (lane >> 2);
                    const int col = wn * 32 + nt * 8 + (lane & 3) * 2;
                    const float b0 = bias ? bias[col] : 0.f;
                    const float b1 = bias ? bias[col + 1] : 0.f;
                    int n = n0 + row;
                    if (n < N_NODES)
                        *(half2*)(P + (size_t)n * 128 + col) =
                            __floats2half2_rn(acc[mt][nt][0] + b0, acc[mt][nt][1] + b1);
                    n = n0 + row + 8;
                    if (n < N_NODES)
                        *(half2*)(P + (size_t)n * 128 + col) =
                            __floats2half2_rn(acc[mt][nt][2] + b0, acc[mt][nt][3] + b1);
                }
        }
        __syncthreads();
    }
}

// ---------------------------------------------------------------------------
// Fat persistent edge kernel: 4 groups x 128 threads, 32-edge tiles,
// factorized layer-1, fused Psum, 3 barriers/tile, register-direct scatter.
// ---------------------------------------------------------------------------
#define EOF_W1S   0           // 32 x 136 h = 8704
#define EOF_W2    8704        // 34816
#define EOF_B2    43520
#define EOF_HW    44032
#define EOF_GRP   44544
#define GRP_PS    0           // Psum: 32 x 136 h = 8704
#define GRP_FSM   8704        // 32 x 80 B = 2560
#define GRP_ACT   11264       // 32 x 136 h = 8704
#define GRP_SD    19968       // 2 x 512
#define GRP_SIDX  20992       // 2 x 256
#define GRP_SPART 21504       // 32 x 4 f = 512
#define GRP_SIZE  22016
#define EDGE_SMEM (EOF_GRP + 4 * GRP_SIZE)   // 132608

__global__ void __launch_bounds__(512, 1)
edge_fat_kernel(const float* __restrict__ coords,
                const int* __restrict__ src, const int* __restrict__ dst,
                const __half* __restrict__ gW1e, const __half* __restrict__ gW2e,
                const __half* __restrict__ gW1c, const __half* __restrict__ gW2c,
                const float* __restrict__ be2,
                const float* __restrict__ Wa,  const float* __restrict__ ba,
                const float* __restrict__ bc2,
                const float* __restrict__ Wc3)
{
    extern __shared__ __align__(16) char sm[];
    float* sb2  = (float*)(sm + EOF_B2);
    float* shw  = (float*)(sm + EOF_HW);

    const int tid  = threadIdx.x;
    const int g    = tid >> 7;            // group 0..3
    const int gtid = tid & 127;
    const int bar  = g + 1;
    const int mode = blockIdx.x & 1;
    const int cb   = blockIdx.x >> 1;

    char* grp = sm + EOF_GRP + g * GRP_SIZE;
    __half* Ps  = (__half*)(grp + GRP_PS);
    char*   fsm = grp + GRP_FSM;
    __half* act = (__half*)(grp + GRP_ACT);
    int*    sidx = (int*)(grp + GRP_SIDX);   // [buf*64 + (src32|dst32)]
    float*  spart = (float*)(grp + GRP_SPART);

    const uint32_t fsmU = smem_u32(fsm), actU = smem_u32(act);
    const uint32_t w1sU = smem_u32(sm + EOF_W1S), w2U = smem_u32(sm + EOF_W2);

    const __half* gW1 = mode ? gW1c : gW1e;
    const __half* gW2 = mode ? gW2c : gW2e;
    const __half* gP1 = mode ? g_P1c : g_P1e;
    const __half* gP2 = mode ? g_P2c : g_P2e;
    const float*  b2  = mode ? bc2 : be2;
    const float*  hw  = mode ? Wc3 : Wa;
    const float   hb0 = mode ? 0.f : ba[0];

    for (int i = tid; i < 544; i += 512)
        ((float4*)(sm + EOF_W1S))[i] = ((const float4*)(gW1 + 256 * 136))[i];
    for (int i = tid; i < 2176; i += 512)
        ((float4*)(sm + EOF_W2))[i] = ((const float4*)gW2)[i];
    if (tid < 128) { sb2[tid] = b2[tid]; shw[tid] = hw[tid]; }
    if (gtid < 32) {  // zero-pad fsm cols 20..31 (bytes 40..63)
        *(uint2*)(fsm + gtid * 80 + 40) = make_uint2(0, 0);
        *(uint2*)(fsm + gtid * 80 + 48) = make_uint2(0, 0);
        *(uint2*)(fsm + gtid * 80 + 56) = make_uint2(0, 0);
    }
    __syncthreads();

    const int t0 = cb * 4 + g;            // stream id 0..295 within mode
    float pdx = 0.f, pdy = 0.f, pdz = 0.f, pr = 0.f;

    // ---------------- prologue: gather tile t0 ----------------
    if (gtid < 32) {
        const int e = t0 * 32 + gtid;
        const int s_ = src[e], d_ = dst[e];
        sidx[gtid] = s_; sidx[32 + gtid] = d_;
        pdx = coords[s_ * 3 + 0] - coords[d_ * 3 + 0];
        pdy = coords[s_ * 3 + 1] - coords[d_ * 3 + 1];
        pdz = coords[s_ * 3 + 2] - coords[d_ * 3 + 2];
        pr  = sqrtf(pdx * pdx + pdy * pdy + pdz * pdz);
        if (mode == 1) {
            float* sd = (float*)(grp + GRP_SD);
            sd[4 * gtid + 0] = pdx; sd[4 * gtid + 1] = pdy;
            sd[4 * gtid + 2] = pdz; sd[4 * gtid + 3] = pr;
        }
    }
    GBAR(bar);
    {
#pragma unroll
        for (int i = 0; i < 4; ++i) {
            const int idx = gtid + i * 128;
            const int el = idx >> 4, c = idx & 15;
            uint4 p1 = *(const uint4*)(gP1 + (size_t)sidx[el] * 128 + c * 8);
            uint4 p2 = *(const uint4*)(gP2 + (size_t)sidx[32 + el] * 128 + c * 8);
            *(uint4*)((char*)Ps + el * 272 + c * 16) = hadd2x4(p1, p2);
        }
        {
            const int row = gtid >> 2, part = gtid & 3;
            uint2 v = *(const uint2*)(g_a16 + (size_t)(t0 * 32 + row) * 16 + part * 4);
            *(uint2*)(fsm + row * 80 + 8 + part * 8) = v;
        }
        if (gtid < 32) {
            half2 d0 = __floats2half2_rn(pr, fabsf(pdx));
            half2 d1 = __floats2half2_rn(fabsf(pdy), fabsf(pdz));
            *(uint2*)(fsm + gtid * 80) = make_uint2(*(uint32_t*)&d0, *(uint32_t*)&d1);
        }
    }
    GBAR(bar);

    float acc[2][4][4];
    int buf = 0;
    const int lane = tid & 31;
    const int wn = (tid >> 5) & 3;

    // ---------------- persistent tile loop (3 barriers) ----------------
    for (int t = t0; t < NTILES32; t += NSTREAMS) {
        const int tn = t + NSTREAMS;
        const int nbuf = buf ^ 1;
        const bool pf = (tn < NTILES32);
        uint4 rw[4];
        uint2 aR = make_uint2(0, 0);

        if (pf && gtid < 32) {
            const int e = tn * 32 + gtid;
            const int s_ = src[e], d_ = dst[e];
            sidx[nbuf * 64 + gtid] = s_;
            sidx[nbuf * 64 + 32 + gtid] = d_;
            pdx = coords[s_ * 3 + 0] - coords[d_ * 3 + 0];
            pdy = coords[s_ * 3 + 1] - coords[d_ * 3 + 1];
            pdz = coords[s_ * 3 + 2] - coords[d_ * 3 + 2];
            pr  = sqrtf(pdx * pdx + pdy * pdy + pdz * pdz);
            if (mode == 1) {
                float* sd = (float*)(grp + GRP_SD + nbuf * 512);
                sd[4 * gtid + 0] = pdx; sd[4 * gtid + 1] = pdy;
                sd[4 * gtid + 2] = pdz; sd[4 * gtid + 3] = pr;
            }
        }

        // gather for tn: Psum in registers (indices straight from global)
        if (pf) {
#pragma unroll
            for (int i = 0; i < 4; ++i) {
                const int idx = gtid + i * 128;
                const int el = idx >> 4, c = idx & 15;
                const int e = tn * 32 + el;
                uint4 p1 = *(const uint4*)(gP1 + (size_t)__ldg(src + e) * 128 + c * 8);
                uint4 p2 = *(const uint4*)(gP2 + (size_t)__ldg(dst + e) * 128 + c * 8);
                rw[i] = hadd2x4(p1, p2);
            }
            aR = *(const uint2*)(g_a16 + (size_t)(tn * 32 + (gtid >> 2)) * 16 + (gtid & 3) * 4);
        }

        // G1small: [D|a] @ W1mid, K=32
        zero_acc(acc);
        gemm_g(fsmU, 40, w1sU, 2, acc);

        // E1: act = silu(acc + Psum)
        epi_fuse_g(acc, Ps, act);
        GBAR(bar);   // (1) Psum/fsm reads done; act visible

        // commit tn data, then G2
        if (pf) {
#pragma unroll
            for (int i = 0; i < 4; ++i) {
                const int idx = gtid + i * 128;
                const int el = idx >> 4, c = idx & 15;
                *(uint4*)((char*)Ps + el * 272 + c * 16) = rw[i];
            }
            *(uint2*)(fsm + (gtid >> 2) * 80 + 8 + (gtid & 3) * 8) = aR;
            if (gtid < 32) {
                half2 d0 = __floats2half2_rn(pr, fabsf(pdx));
                half2 d1 = __floats2half2_rn(fabsf(pdy), fabsf(pdz));
                *(uint2*)(fsm + gtid * 80) = make_uint2(*(uint32_t*)&d0, *(uint32_t*)&d1);
            }
        }
        zero_acc(acc);
        gemm_g(actU, 136, w2U, 8, acc);

        // E2a: silu in-place + partial head dot
        {
            float part[4] = {0.f, 0.f, 0.f, 0.f};
#pragma unroll
            for (int mt = 0; mt < 2; ++mt)
#pragma unroll
                for (int nt = 0; nt < 4; ++nt) {
                    const int col = wn * 32 + nt * 8 + (lane & 3) * 2;
                    const float b0 = sb2[col], b1v = sb2[col + 1];
                    const float w0 = shw[col], w1 = shw[col + 1];
                    const float v0 = silu_f(acc[mt][nt][0] + b0);
                    const float v1 = silu_f(acc[mt][nt][1] + b1v);
                    const float v2 = silu_f(acc[mt][nt][2] + b0);
                    const float v3 = silu_f(acc[mt][nt][3] + b1v);
                    acc[mt][nt][0] = v0; acc[mt][nt][1] = v1;
                    acc[mt][nt][2] = v2; acc[mt][nt][3] = v3;
                    part[mt * 2 + 0] = fmaf(v0, w0, fmaf(v1, w1, part[mt * 2 + 0]));
                    part[mt * 2 + 1] = fmaf(v2, w0, fmaf(v3, w1, part[mt * 2 + 1]));
                }
#pragma unroll
            for (int k = 0; k < 4; ++k) {
                part[k] += __shfl_xor_sync(0xFFFFFFFFu, part[k], 1);
                part[k] += __shfl_xor_sync(0xFFFFFFFFu, part[k], 2);
            }
            if ((lane & 3) == 0) {
                const int rsel = lane >> 2;
                spart[( 0 + rsel) * 4 + wn] = part[0];
                spart[( 8 + rsel) * 4 + wn] = part[1];
                spart[(16 + rsel) * 4 + wn] = part[2];
                spart[(24 + rsel) * 4 + wn] = part[3];
            }
        }
        GBAR(bar);   // (2) spart visible

        if (mode == 0) {
            // per-quad att (variant v = lane&3 -> row rv)
            const int v = lane & 3;
            const int rv = (v >> 1) * 16 + (v & 1) * 8 + (lane >> 2);
            const float dotv = spart[rv * 4 + 0] + spart[rv * 4 + 1]
                             + spart[rv * 4 + 2] + spart[rv * 4 + 3];
            const float attv = sigmoid_f(dotv + hb0);
            float attArr[4];
#pragma unroll
            for (int k = 0; k < 4; ++k)
                attArr[k] = __shfl_sync(0xFFFFFFFFu, attv, (lane & ~3) | k);
#pragma unroll
            for (int mt = 0; mt < 2; ++mt)
#pragma unroll
                for (int rr = 0; rr < 2; ++rr) {
                    const int row = mt * 16 + rr * 8 + (lane >> 2);
                    const float att = attArr[mt * 2 + rr];
                    const int d_ = sidx[buf * 64 + 32 + row];
#pragma unroll
                    for (int nt = 0; nt < 4; ++nt) {
                        float s0 = att * acc[mt][nt][2 * rr + 0];
                        float s1 = att * acc[mt][nt][2 * rr + 1];
                        float n0 = __shfl_xor_sync(0xFFFFFFFFu, s0, 1);
                        float n1 = __shfl_xor_sync(0xFFFFFFFFu, s1, 1);
                        if ((lane & 1) == 0) {
                            const int col = wn * 32 + nt * 8 + (lane & 3) * 2;
                            red_add_v4(g_hagg + (size_t)d_ * 128 + col, s0, s1, n0, n1);
                        }
                    }
                }
        } else {
            if (gtid < 32) {
                const float dot = spart[gtid * 4 + 0] + spart[gtid * 4 + 1]
                                + spart[gtid * 4 + 2] + spart[gtid * 4 + 3];
                const float* sd = (const float*)(grp + GRP_SD + buf * 512);
                const float dx = sd[4 * gtid + 0], dy = sd[4 * gtid + 1];
                const float dz = sd[4 * gtid + 2], r  = sd[4 * gtid + 3];
                const float gg = dot / (r + 1.f);
                const int d_ = sidx[buf * 64 + 32 + gtid];
                atomicAdd(&g_xagg[d_ * 3 + 0], gg * dx);
                atomicAdd(&g_xagg[d_ * 3 + 1], gg * dy);
                atomicAdd(&g_xagg[d_ * 3 + 2], gg * dz);
            }
        }
        GBAR(bar);   // (3) end of tile
        buf = nbuf;
    }
}

// ---------------------------------------------------------------------------
// Persistent node kernel (unchanged)
// ---------------------------------------------------------------------------
#define NOF_W1   0
#define NOF_W2   69632
#define NOF_A    104448
#define NOF_ACT  172032
#define NOF_B    206848
#define NODE_SMEM 207872

__global__ void __launch_bounds__(512, 1)
node_kernel(const float* __restrict__ hmat, const float* __restrict__ coords,
            const float* __restrict__ bn1, const float* __restrict__ bn2,
            float* __restrict__ out)
{
    extern __shared__ __align__(16) char sm[];
    __half* sW1 = (__half*)(sm + NOF_W1);
    __half* sW2 = (__half*)(sm + NOF_W2);
    char*   aB  = sm + NOF_A;
    __half* act = (__half*)(sm + NOF_ACT);
    float* sb1  = (float*)(sm + NOF_B);
    float* sb2  = sb1 + 128;

    const uint32_t aU = smem_u32(aB), w1U = smem_u32(sW1);
    const uint32_t w2U = smem_u32(sW2), actU = smem_u32(act);
    const int tid = threadIdx.x;

    for (int i = tid; i < 4352; i += 512) ((float4*)sW1)[i] = ((const float4*)g_Wn1)[i];
    for (int i = tid; i < 2176; i += 512) ((float4*)sW2)[i] = ((const float4*)g_Wn2)[i];
    if (tid < 128) { sb1[tid] = bn1[tid]; sb2[tid] = bn2[tid]; }
    __syncthreads();

    const int lane = tid & 31;
    const int wid  = tid >> 5;
    const int wm = wid & 3, wn = wid >> 2;
    float acc[2][4][4];

    for (int t = blockIdx.x; t < NODE_TILES; t += 148) {
        const int n0 = t * 128;

#pragma unroll
        for (int i = 0; i < 4; ++i) {
            const int idx = tid + i * 512;
            const int el = idx >> 4, c = idx & 15;
            const int n = n0 + el;
            float4 v = make_float4(0.f, 0.f, 0.f, 0.f);
            if (n < N_NODES) v = *(const float4*)(g_h16 + (size_t)n * 128 + c * 8);
            *(float4*)(aB + el * 528 + c * 16) = v;
        }
#pragma unroll
        for (int i = 0; i < 8; ++i) {
            const int idx = tid + i * 512;
            const int el = idx >> 5, c = idx & 31;
            const int n = n0 + el;
            float4 v = make_float4(0.f, 0.f, 0.f, 0.f);
            if (n < N_NODES) v = ((const float4*)g_hagg)[(size_t)n * 32 + c];
            half2 h0 = __floats2half2_rn(v.x, v.y);
            half2 h1 = __floats2half2_rn(v.z, v.w);
            *(uint2*)(aB + el * 528 + 256 + c * 8) =
                make_uint2(*(uint32_t*)&h0, *(uint32_t*)&h1);
        }
        __syncthreads();

        zero_acc32(acc);
        gemm512(aU, 264, w1U, 16, acc);
        __syncthreads();
        {
#pragma unroll
            for (int mt = 0; mt < 2; ++mt)
#pragma unroll
                for (int nt = 0; nt < 4; ++nt) {
                    const int row = wm * 32 + mt * 16 + (lane >> 2);
                    const int col = wn * 32 + nt * 8 + (lane & 3) * 2;
                    const float b0 = sb1[col], b1v = sb1[col + 1];
                    *(half2*)(act + row * 136 + col) =
                        __floats2half2_rn(silu_f(acc[mt][nt][0] + b0), silu_f(acc[mt][nt][1] + b1v));
                    *(half2*)(act + (row + 8) * 136 + col) =
                        __floats2half2_rn(silu_f(acc[mt][nt][2] + b0), silu_f(acc[mt][nt][3] + b1v));
                }
        }
        __syncthreads();

        zero_acc32(acc);
        gemm512(actU, 136, w2U, 8, acc);

#pragma unroll
        for (int mt = 0; mt < 2; ++mt)
#pragma unroll
            for (int nt = 0; nt < 4; ++nt) {
                const int row = wm * 32 + mt * 16 + (lane >> 2);
                const int col = wn * 32 + nt * 8 + (lane & 3) * 2;
                const float b0 = sb2[col], b1v = sb2[col + 1];
                int n = n0 + row;
                if (n < N_NODES) {
                    float2 hv = *(const float2*)(hmat + (size_t)n * 128 + col);
                    *(float2*)(out + (size_t)n * 128 + col) =
                        make_float2(hv.x + acc[mt][nt][0] + b0, hv.y + acc[mt][nt][1] + b1v);
                }
                n = n0 + row + 8;
                if (n < N_NODES) {
                    float2 hv = *(const float2*)(hmat + (size_t)n * 128 + col);
                    *(float2*)(out + (size_t)n * 128 + col) =
                        make_float2(hv.x + acc[mt][nt][2] + b0, hv.y + acc[mt][nt][3] + b1v);
                }
            }

        if (tid < 128) {
            const int n = n0 + tid;
            if (n < N_NODES) {
                const size_t base = (size_t)N_NODES * 128;
                out[base + n * 3 + 0] = coords[n * 3 + 0] + g_xagg[n * 3 + 0];
                out[base + n * 3 + 1] = coords[n * 3 + 1] + g_xagg[n * 3 + 1];
                out[base + n * 3 + 2] = coords[n * 3 + 2] + g_xagg[n * 3 + 2];
            }
        }
        __syncthreads();
    }
}

// ---------------------------------------------------------------------------
extern "C" void kernel_launch(void* const* d_in, const int* in_sizes, int n_in,
                              void* d_out, int out_size)
{
    const float* h      = (const float*)d_in[0];
    const float* coords = (const float*)d_in[1];
    const float* a      = (const float*)d_in[2];
    const int*   src    = (const int*)d_in[3];
    const int*   dst    = (const int*)d_in[4];
    const float* We1 = (const float*)d_in[5];
    const float* be1 = (const float*)d_in[6];
    const float* We2 = (const float*)d_in[7];
    const float* be2 = (const float*)d_in[8];
    const float* Wa  = (const float*)d_in[9];
    const float* ba  = (const float*)d_in[10];
    const float* Wn1 = (const float*)d_in[11];
    const float* bn1 = (const float*)d_in[12];
    const float* Wn2 = (const float*)d_in[13];
    const float* bn2 = (const float*)d_in[14];
    const float* Wc1 = (const float*)d_in[15];
    const float* bc1 = (const float*)d_in[16];
    const float* Wc2 = (const float*)d_in[17];
    const float* bc2 = (const float*)d_in[18];
    const float* Wc3 = (const float*)d_in[19];
    float* out = (float*)d_out;

    __half *dW1e, *dW1c, *dWe2, *dWc2;
    cudaGetSymbolAddress((void**)&dW1e, g_W1e);
    cudaGetSymbolAddress((void**)&dW1c, g_W1c);
    cudaGetSymbolAddress((void**)&dWe2, g_We2);
    cudaGetSymbolAddress((void**)&dWc2, g_Wc2);

    cudaFuncSetAttribute(precompute_kernel, cudaFuncAttributeMaxDynamicSharedMemorySize, PC_SMEM);
    cudaFuncSetAttribute(edge_fat_kernel, cudaFuncAttributeMaxDynamicSharedMemorySize, EDGE_SMEM);
    cudaFuncSetAttribute(node_kernel, cudaFuncAttributeMaxDynamicSharedMemorySize, NODE_SMEM);

    prep_kernel<<<1024, 256>>>(h, a, We1, Wc1, We2, Wc2, Wn1, Wn2);
    precompute_kernel<<<148, 512, PC_SMEM>>>(be1, bc1);
    edge_fat_kernel<<<148, 512, EDGE_SMEM>>>(
        coords, src, dst, dW1e, dWe2, dW1c, dWc2,
        be2, Wa, ba, bc2, Wc3);
    node_kernel<<<148, 512, NODE_SMEM>>>(h, coords, bn1, bn2, out);
}